// round 3
// baseline (speedup 1.0000x reference)
#include <cuda_runtime.h>
#include <math.h>

#define NN 10000
#define EE 160000
#define FIN 70
#define HHID 256
#define NHEADS 4
#define D1 1024   // HEADS*HID

// ---------------- device scratch (no allocations allowed) ----------------
__device__ float g_h1[NN * D1];      // layer-1 linear output  [N,4,256]
__device__ float g_x1[NN * D1];      // relu(agg1 + b1)        [N,1024]
__device__ float g_as1[NN * 4];
__device__ float g_ad1[NN * 4];
__device__ float g_h2[NN * HHID];    // layer-2 linear output
__device__ float g_as2[NN];
__device__ float g_ad2[NN];
__device__ float g_pooled[HHID];
__device__ int   g_deg[NN];
__device__ int   g_offs[NN + 1];
__device__ int   g_cursor[NN];
__device__ int   g_srcs[EE];

// ---------------- small utils ----------------
__global__ void k_zero() {
    int i = blockIdx.x * blockDim.x + threadIdx.x;
    if (i < NN)  g_deg[i] = 0;
    if (i < HHID) g_pooled[i] = 0.f;
}

__global__ void k_hist(const int* __restrict__ ei) {
    int i = blockIdx.x * blockDim.x + threadIdx.x;
    if (i < EE) atomicAdd(&g_deg[ei[EE + i]], 1);
}

// single-block exclusive scan over g_deg -> g_offs / g_cursor
__global__ void k_scan() {
    __shared__ int sbuf[1024];
    int t = threadIdx.x;
    int base = t * 10;
    int loc[10];
    int sum = 0;
#pragma unroll
    for (int q = 0; q < 10; q++) {
        int idx = base + q;
        int v = (idx < NN) ? g_deg[idx] : 0;
        loc[q] = sum; sum += v;
    }
    sbuf[t] = sum;
    __syncthreads();
    for (int off = 1; off < 1024; off <<= 1) {
        int tmp = (t >= off) ? sbuf[t - off] : 0;
        __syncthreads();
        sbuf[t] += tmp;
        __syncthreads();
    }
    int excl = sbuf[t] - sum;
#pragma unroll
    for (int q = 0; q < 10; q++) {
        int idx = base + q;
        if (idx < NN) { int o = excl + loc[q]; g_offs[idx] = o; g_cursor[idx] = o; }
    }
    if (t == 1023) g_offs[NN] = sbuf[1023];
}

__global__ void k_scatter(const int* __restrict__ ei) {
    int i = blockIdx.x * blockDim.x + threadIdx.x;
    if (i < EE) {
        int dnode = ei[EE + i];
        int pos = atomicAdd(&g_cursor[dnode], 1);
        g_srcs[pos] = ei[i];
    }
}

// ---------------- GEMM1: x[N,70] @ W1[70,1024] -> g_h1 ----------------
// 4 nodes per block, 256 threads, each thread covers cols tid + 256*j
__global__ void k_gemm1(const float* __restrict__ x, const float* __restrict__ W1) {
    __shared__ float xs[4][FIN];
    int tid = threadIdx.x;
    int n0 = blockIdx.x * 4;
    for (int i = tid; i < 4 * FIN; i += 256)
        xs[i / FIN][i % FIN] = x[n0 * FIN + i];   // rows contiguous
    __syncthreads();
    float acc[4][4] = {};
    for (int k = 0; k < FIN; k++) {
        float w[4];
#pragma unroll
        for (int j = 0; j < 4; j++) w[j] = W1[k * D1 + j * 256 + tid];
#pragma unroll
        for (int n = 0; n < 4; n++) {
            float xv = xs[n][k];
#pragma unroll
            for (int j = 0; j < 4; j++) acc[n][j] += xv * w[j];
        }
    }
#pragma unroll
    for (int n = 0; n < 4; n++)
#pragma unroll
        for (int j = 0; j < 4; j++)
            g_h1[(n0 + n) * D1 + j * 256 + tid] = acc[n][j];
}

// ---------------- attention logits layer 1 ----------------
// 1 warp per (node, head): grid 10000, 128 threads
__global__ void k_att1(const float* __restrict__ as, const float* __restrict__ adv) {
    int wid = threadIdx.x >> 5, lane = threadIdx.x & 31;
    int d = blockIdx.x;
    const float* h = g_h1 + d * D1 + wid * HHID;
    float ps = 0.f, pd = 0.f;
    for (int c = lane; c < HHID; c += 32) {
        float hv = h[c];
        ps += hv * as[wid * HHID + c];
        pd += hv * adv[wid * HHID + c];
    }
#pragma unroll
    for (int o = 16; o; o >>= 1) {
        ps += __shfl_xor_sync(0xffffffffu, ps, o);
        pd += __shfl_xor_sync(0xffffffffu, pd, o);
    }
    if (lane == 0) { g_as1[d * 4 + wid] = ps; g_ad1[d * 4 + wid] = pd; }
}

// ---------------- block reductions (256 threads / 8 warps) ----------------
__device__ __forceinline__ float blk_max(float v, volatile float* wred, int lane, int wid) {
#pragma unroll
    for (int o = 16; o; o >>= 1) v = fmaxf(v, __shfl_xor_sync(0xffffffffu, v, o));
    if (lane == 0) wred[wid] = v;
    __syncthreads();
    if (wid == 0) {
        float r = (lane < 8) ? wred[lane] : -3e38f;
#pragma unroll
        for (int o = 4; o; o >>= 1) r = fmaxf(r, __shfl_xor_sync(0xffffffffu, r, o));
        if (lane == 0) wred[0] = r;
    }
    __syncthreads();
    float r = wred[0];
    __syncthreads();
    return r;
}

__device__ __forceinline__ float blk_sum(float v, volatile float* wred, int lane, int wid) {
#pragma unroll
    for (int o = 16; o; o >>= 1) v += __shfl_xor_sync(0xffffffffu, v, o);
    if (lane == 0) wred[wid] = v;
    __syncthreads();
    if (wid == 0) {
        float r = (lane < 8) ? wred[lane] : 0.f;
#pragma unroll
        for (int o = 4; o; o >>= 1) r += __shfl_xor_sync(0xffffffffu, r, o);
        if (lane == 0) wred[0] = r;
    }
    __syncthreads();
    float r = wred[0];
    __syncthreads();
    return r;
}

// ---------------- layer-1 segment softmax + aggregation ----------------
// one block per destination node; thread tid handles channel tid of every head
__global__ void k_agg1(const float* __restrict__ b1) {
    int d = blockIdx.x, tid = threadIdx.x, lane = tid & 31, wid = tid >> 5;
    __shared__ float wred[8];
    __shared__ float alpha[64][4];
    int beg = g_offs[d];
    int cnt = g_offs[d + 1] - beg;
    int deg = cnt + 1;                    // + self loop
    float ad[4];
#pragma unroll
    for (int j = 0; j < 4; j++) ad[j] = g_ad1[d * 4 + j];

    float m[4] = { -3e38f, -3e38f, -3e38f, -3e38f };
    for (int i = tid; i < deg; i += 256) {
        int s = (i < cnt) ? g_srcs[beg + i] : d;
#pragma unroll
        for (int j = 0; j < 4; j++) {
            float e = g_as1[s * 4 + j] + ad[j];
            e = e > 0.f ? e : 0.2f * e;
            m[j] = fmaxf(m[j], e);
        }
    }
#pragma unroll
    for (int j = 0; j < 4; j++) m[j] = blk_max(m[j], wred, lane, wid);

    float ssum[4] = { 0.f, 0.f, 0.f, 0.f };
    for (int i = tid; i < deg; i += 256) {
        int s = (i < cnt) ? g_srcs[beg + i] : d;
#pragma unroll
        for (int j = 0; j < 4; j++) {
            float e = g_as1[s * 4 + j] + ad[j];
            e = e > 0.f ? e : 0.2f * e;
            ssum[j] += expf(e - m[j]);
        }
    }
    float inv[4];
#pragma unroll
    for (int j = 0; j < 4; j++) {
        float s2 = blk_sum(ssum[j], wred, lane, wid);
        inv[j] = 1.0f / (s2 + 1e-16f);
    }

    float acc[4] = { 0.f, 0.f, 0.f, 0.f };
    for (int c0 = 0; c0 < deg; c0 += 64) {
        int chunk = min(64, deg - c0);
        __syncthreads();
        for (int t = tid; t < chunk * 4; t += 256) {
            int il = t >> 2, j = t & 3;
            int i = c0 + il;
            int s = (i < cnt) ? g_srcs[beg + i] : d;
            float e = g_as1[s * 4 + j] + ad[j];
            e = e > 0.f ? e : 0.2f * e;
            alpha[il][j] = expf(e - m[j]) * inv[j];
        }
        __syncthreads();
        for (int il = 0; il < chunk; il++) {
            int i = c0 + il;
            int s = (i < cnt) ? g_srcs[beg + i] : d;
            const float* h = g_h1 + s * D1 + tid;
            acc[0] += alpha[il][0] * h[0];
            acc[1] += alpha[il][1] * h[256];
            acc[2] += alpha[il][2] * h[512];
            acc[3] += alpha[il][3] * h[768];
        }
    }
#pragma unroll
    for (int j = 0; j < 4; j++) {
        float v = acc[j] + b1[j * 256 + tid];
        g_x1[d * D1 + j * 256 + tid] = v > 0.f ? v : 0.f;   // ReLU after layer 1
    }
}

// ---------------- GEMM2: x1[N,1024] @ W2[1024,256] -> g_h2 ----------------
#define BM 64
#define BN 128
#define KC 32
__global__ void k_gemm2(const float* __restrict__ W2) {
    __shared__ float As[KC][BM + 1];   // [k][row] padded
    __shared__ float Bs[KC][BN];
    int tid = threadIdx.x;
    int tx = tid & 31;        // col group
    int ty = tid >> 5;        // 0..7
    int row0 = blockIdx.x * BM;
    int col0 = blockIdx.y * BN;
    float acc[8][4] = {};
    for (int kc = 0; kc < D1; kc += KC) {
#pragma unroll
        for (int q = 0; q < 8; q++) {           // A: 64x32
            int i = tid + q * 256;
            int kl = i & 31;
            int rl = i >> 5;
            int row = row0 + rl;
            As[kl][rl] = (row < NN) ? g_x1[row * D1 + kc + kl] : 0.0f;
        }
#pragma unroll
        for (int q = 0; q < 16; q++) {          // B: 32x128
            int i = tid + q * 256;
            int cl = i & 127;
            int kl = i >> 7;
            Bs[kl][cl] = W2[(kc + kl) * HHID + col0 + cl];
        }
        __syncthreads();
#pragma unroll
        for (int kk = 0; kk < KC; kk++) {
            float4 b = *reinterpret_cast<const float4*>(&Bs[kk][tx * 4]);
#pragma unroll
            for (int i = 0; i < 8; i++) {
                float a = As[kk][ty + 8 * i];
                acc[i][0] += a * b.x; acc[i][1] += a * b.y;
                acc[i][2] += a * b.z; acc[i][3] += a * b.w;
            }
        }
        __syncthreads();
    }
#pragma unroll
    for (int i = 0; i < 8; i++) {
        int row = row0 + ty + 8 * i;
        if (row < NN) {
            float4 v = make_float4(acc[i][0], acc[i][1], acc[i][2], acc[i][3]);
            *reinterpret_cast<float4*>(&g_h2[row * HHID + col0 + tx * 4]) = v;
        }
    }
}

// ---------------- attention logits layer 2 (1 head) ----------------
__global__ void k_att2(const float* __restrict__ as, const float* __restrict__ adv) {
    int wid = threadIdx.x >> 5, lane = threadIdx.x & 31;
    int d = blockIdx.x * 4 + wid;
    if (d >= NN) return;
    const float* h = g_h2 + d * HHID;
    float ps = 0.f, pd = 0.f;
    for (int c = lane; c < HHID; c += 32) {
        float hv = h[c];
        ps += hv * as[c];
        pd += hv * adv[c];
    }
#pragma unroll
    for (int o = 16; o; o >>= 1) {
        ps += __shfl_xor_sync(0xffffffffu, ps, o);
        pd += __shfl_xor_sync(0xffffffffu, pd, o);
    }
    if (lane == 0) { g_as2[d] = ps; g_ad2[d] = pd; }
}

// ---------------- layer-2 aggregation + ReLU + mean pool ----------------
__global__ void k_agg2(const float* __restrict__ b2) {
    int d = blockIdx.x, tid = threadIdx.x, lane = tid & 31, wid = tid >> 5;
    __shared__ float wred[8];
    __shared__ float alpha[256];
    int beg = g_offs[d], cnt = g_offs[d + 1] - beg, deg = cnt + 1;
    float ad = g_ad2[d];

    float m = -3e38f;
    for (int i = tid; i < deg; i += 256) {
        int s = (i < cnt) ? g_srcs[beg + i] : d;
        float e = g_as2[s] + ad; e = e > 0.f ? e : 0.2f * e;
        m = fmaxf(m, e);
    }
    m = blk_max(m, wred, lane, wid);

    float ss = 0.f;
    for (int i = tid; i < deg; i += 256) {
        int s = (i < cnt) ? g_srcs[beg + i] : d;
        float e = g_as2[s] + ad; e = e > 0.f ? e : 0.2f * e;
        ss += expf(e - m);
    }
    ss = blk_sum(ss, wred, lane, wid);
    float inv = 1.0f / (ss + 1e-16f);

    float acc = 0.f;
    for (int c0 = 0; c0 < deg; c0 += 256) {
        int chunk = min(256, deg - c0);
        __syncthreads();
        if (tid < chunk) {
            int i = c0 + tid;
            int s = (i < cnt) ? g_srcs[beg + i] : d;
            float e = g_as2[s] + ad; e = e > 0.f ? e : 0.2f * e;
            alpha[tid] = expf(e - m) * inv;
        }
        __syncthreads();
        for (int il = 0; il < chunk; il++) {
            int i = c0 + il;
            int s = (i < cnt) ? g_srcs[beg + i] : d;
            acc += alpha[il] * g_h2[s * HHID + tid];
        }
    }
    float v = acc + b2[tid];
    v = v > 0.f ? v : 0.f;                       // ReLU after layer 2
    atomicAdd(&g_pooled[tid], v * (1.0f / NN));  // mean pool
}

// ---------------- final MLP: gelu(pooled@Wv1+bv1)@Wv2+bv2 ----------------
__global__ void k_final(const float* __restrict__ Wv1, const float* __restrict__ bv1,
                        const float* __restrict__ Wv2, const float* __restrict__ bv2,
                        float* __restrict__ out) {
    __shared__ float sp[HHID];
    __shared__ float wred[4];
    int t = threadIdx.x;   // 128 threads
    for (int c = t; c < HHID; c += 128) sp[c] = g_pooled[c];
    __syncthreads();
    float a = 0.f;
    for (int k = 0; k < HHID; k++) a += sp[k] * Wv1[k * 128 + t];
    a += bv1[t];
    float g = a * normcdff(a);   // exact GELU
    float v = g * Wv2[t];
    int lane = t & 31, wid = t >> 5;
#pragma unroll
    for (int o = 16; o; o >>= 1) v += __shfl_xor_sync(0xffffffffu, v, o);
    if (lane == 0) wred[wid] = v;
    __syncthreads();
    if (t == 0) out[0] = wred[0] + wred[1] + wred[2] + wred[3] + bv2[0];
}

// ---------------- launch ----------------
extern "C" void kernel_launch(void* const* d_in, const int* in_sizes, int n_in,
                              void* d_out, int out_size) {
    const float* x       = (const float*)d_in[0];
    const int*   ei      = (const int*)  d_in[1];
    // d_in[2] edge_attr unused (GATConv built without edge_dim)
    const float* W1      = (const float*)d_in[3];
    const float* att_s1  = (const float*)d_in[4];
    const float* att_d1  = (const float*)d_in[5];
    const float* b1      = (const float*)d_in[6];
    const float* W2      = (const float*)d_in[7];
    const float* att_s2  = (const float*)d_in[8];
    const float* att_d2  = (const float*)d_in[9];
    const float* b2      = (const float*)d_in[10];
    const float* Wv1     = (const float*)d_in[11];
    const float* bv1     = (const float*)d_in[12];
    const float* Wv2     = (const float*)d_in[13];
    const float* bv2     = (const float*)d_in[14];
    float* out = (float*)d_out;

    k_zero<<<(NN + 255) / 256, 256>>>();
    k_hist<<<(EE + 255) / 256, 256>>>(ei);
    k_scan<<<1, 1024>>>();
    k_scatter<<<(EE + 255) / 256, 256>>>(ei);

    k_gemm1<<<NN / 4, 256>>>(x, W1);
    k_att1<<<NN, 128>>>(att_s1, att_d1);
    k_agg1<<<NN, 256>>>(b1);

    dim3 g2((NN + BM - 1) / BM, HHID / BN);
    k_gemm2<<<g2, 256>>>(W2);
    k_att2<<<(NN + 3) / 4, 128>>>(att_s2, att_d2);
    k_agg2<<<NN, 256>>>(b2);

    k_final<<<1, 128>>>(Wv1, bv1, Wv2, bv2, out);
}

// round 6
// speedup vs baseline: 1.0782x; 1.0782x over previous
#include <cuda_runtime.h>
#include <cuda_bf16.h>
#include <math.h>

#define NN 10000
#define EE 160000
#define FIN 70
#define HHID 256
#define NHEADS 4
#define D1 1024   // HEADS*HID

typedef unsigned long long u64;

// ---------------- packed f32x2 helpers (sm_103a FFMA2) ----------------
__device__ __forceinline__ u64 pack2(float x, float y) {
    u64 r; asm("mov.b64 %0,{%1,%2};" : "=l"(r) : "f"(x), "f"(y)); return r;
}
__device__ __forceinline__ float2 unpack2(u64 v) {
    float2 f; asm("mov.b64 {%0,%1},%2;" : "=f"(f.x), "=f"(f.y) : "l"(v)); return f;
}
__device__ __forceinline__ void fma2(u64& c, u64 a, u64 b) {
    asm("fma.rn.f32x2 %0,%1,%2,%0;" : "+l"(c) : "l"(a), "l"(b));
}

// ---------------- device scratch (no allocations allowed) ----------------
__device__ __nv_bfloat16 g_h1b[NN * D1];   // layer-1 linear output (bf16)
__device__ float g_x1[NN * D1];            // relu(agg1 + b1)  (fp32, GEMM2 A)
__device__ float g_as1[NN * 4];
__device__ float g_ad1[NN * 4];
__device__ __nv_bfloat16 g_h2b[NN * HHID]; // layer-2 linear output (bf16)
__device__ float g_as2[NN];
__device__ float g_ad2[NN];
__device__ float g_pooled[HHID];
__device__ int   g_deg[NN];
__device__ int   g_offs[NN + 1];
__device__ int   g_cursor[NN];
__device__ int   g_srcs[EE];

// ---------------- small utils ----------------
__global__ void k_zero() {
    int i = blockIdx.x * blockDim.x + threadIdx.x;
    if (i < NN)  g_deg[i] = 0;
    if (i < HHID) g_pooled[i] = 0.f;
}

__global__ void k_hist(const int* __restrict__ ei) {
    int i = blockIdx.x * blockDim.x + threadIdx.x;
    if (i < EE) atomicAdd(&g_deg[ei[EE + i]], 1);
}

// single-block exclusive scan over g_deg -> g_offs / g_cursor
__global__ void k_scan() {
    __shared__ int sbuf[1024];
    int t = threadIdx.x;
    int base = t * 10;
    int loc[10];
    int sum = 0;
#pragma unroll
    for (int q = 0; q < 10; q++) {
        int idx = base + q;
        int v = (idx < NN) ? g_deg[idx] : 0;
        loc[q] = sum; sum += v;
    }
    sbuf[t] = sum;
    __syncthreads();
    for (int off = 1; off < 1024; off <<= 1) {
        int tmp = (t >= off) ? sbuf[t - off] : 0;
        __syncthreads();
        sbuf[t] += tmp;
        __syncthreads();
    }
    int excl = sbuf[t] - sum;
#pragma unroll
    for (int q = 0; q < 10; q++) {
        int idx = base + q;
        if (idx < NN) { int o = excl + loc[q]; g_offs[idx] = o; g_cursor[idx] = o; }
    }
    if (t == 1023) g_offs[NN] = sbuf[1023];
}

__global__ void k_scatter(const int* __restrict__ ei) {
    int i = blockIdx.x * blockDim.x + threadIdx.x;
    if (i < EE) {
        int dnode = ei[EE + i];
        int pos = atomicAdd(&g_cursor[dnode], 1);
        g_srcs[pos] = ei[i];
    }
}

// ---------------- GEMM1: x[N,70] @ W1[70,1024] -> g_h1b (bf16) ----------
// 16 nodes per block (node-pair f32x2 accumulators), 256 threads.
// thread covers cols tid + 256*j (head j, channel tid).
#define NPB 16
__global__ void k_gemm1(const float* __restrict__ x, const float* __restrict__ W1) {
    __shared__ float xs[FIN][NPB];   // [k][node], node pairs 8B-aligned
    int tid = threadIdx.x;
    int n0 = blockIdx.x * NPB;
    for (int i = tid; i < NPB * FIN; i += 256) {
        int n = i / FIN, k = i - n * FIN;
        xs[k][n] = x[(n0 + n) * FIN + k];
    }
    __syncthreads();
    u64 acc[8][4];
#pragma unroll
    for (int p = 0; p < 8; p++)
#pragma unroll
        for (int j = 0; j < 4; j++) acc[p][j] = 0ull;

    for (int k = 0; k < FIN; k++) {
        u64 wd[4];
#pragma unroll
        for (int j = 0; j < 4; j++) {
            float w = W1[k * D1 + j * 256 + tid];
            wd[j] = pack2(w, w);
        }
#pragma unroll
        for (int p = 0; p < 8; p++) {
            u64 xp = *reinterpret_cast<const u64*>(&xs[k][2 * p]);   // {x_n, x_{n+1}}
#pragma unroll
            for (int j = 0; j < 4; j++) fma2(acc[p][j], xp, wd[j]);
        }
    }
#pragma unroll
    for (int p = 0; p < 8; p++)
#pragma unroll
        for (int j = 0; j < 4; j++) {
            float2 v = unpack2(acc[p][j]);
            g_h1b[(n0 + 2 * p)     * D1 + j * 256 + tid] = __float2bfloat16(v.x);
            g_h1b[(n0 + 2 * p + 1) * D1 + j * 256 + tid] = __float2bfloat16(v.y);
        }
}

// ---------------- attention logits layer 1 (reads bf16 h1) -------------
// 1 warp per (node, head): grid 10000, 128 threads
__global__ void k_att1(const float* __restrict__ as, const float* __restrict__ adv) {
    int wid = threadIdx.x >> 5, lane = threadIdx.x & 31;
    int d = blockIdx.x;
    const __nv_bfloat162* hb = reinterpret_cast<const __nv_bfloat162*>(g_h1b) + d * 512 + wid * 128;
    const float2* as2 = reinterpret_cast<const float2*>(as)  + wid * 128;
    const float2* ad2 = reinterpret_cast<const float2*>(adv) + wid * 128;
    float ps = 0.f, pd = 0.f;
#pragma unroll
    for (int t = 0; t < 4; t++) {
        int p = lane + 32 * t;
        float2 f = __bfloat1622float2(hb[p]);
        float2 a = as2[p], b = ad2[p];
        ps += f.x * a.x + f.y * a.y;
        pd += f.x * b.x + f.y * b.y;
    }
#pragma unroll
    for (int o = 16; o; o >>= 1) {
        ps += __shfl_xor_sync(0xffffffffu, ps, o);
        pd += __shfl_xor_sync(0xffffffffu, pd, o);
    }
    if (lane == 0) { g_as1[d * 4 + wid] = ps; g_ad1[d * 4 + wid] = pd; }
}

// ---------------- block reductions (256 threads / 8 warps) ----------------
__device__ __forceinline__ float blk_max(float v, volatile float* wred, int lane, int wid) {
#pragma unroll
    for (int o = 16; o; o >>= 1) v = fmaxf(v, __shfl_xor_sync(0xffffffffu, v, o));
    if (lane == 0) wred[wid] = v;
    __syncthreads();
    if (wid == 0) {
        float r = (lane < 8) ? wred[lane] : -3e38f;
#pragma unroll
        for (int o = 4; o; o >>= 1) r = fmaxf(r, __shfl_xor_sync(0xffffffffu, r, o));
        if (lane == 0) wred[0] = r;
    }
    __syncthreads();
    float r = wred[0];
    __syncthreads();
    return r;
}

__device__ __forceinline__ float blk_sum(float v, volatile float* wred, int lane, int wid) {
#pragma unroll
    for (int o = 16; o; o >>= 1) v += __shfl_xor_sync(0xffffffffu, v, o);
    if (lane == 0) wred[wid] = v;
    __syncthreads();
    if (wid == 0) {
        float r = (lane < 8) ? wred[lane] : 0.f;
#pragma unroll
        for (int o = 4; o; o >>= 1) r += __shfl_xor_sync(0xffffffffu, r, o);
        if (lane == 0) wred[0] = r;
    }
    __syncthreads();
    float r = wred[0];
    __syncthreads();
    return r;
}

// ---------------- layer-1 segment softmax + aggregation (bf16 gather) ---
// one block per destination node; thread tid handles bf162-pairs tid and tid+256
// (pair p covers channels 2p,2p+1 of the 1024; head(p) = p>>7)
__global__ void k_agg1(const float* __restrict__ b1) {
    int d = blockIdx.x, tid = threadIdx.x, lane = tid & 31, wid = tid >> 5;
    __shared__ float wred[8];
    __shared__ float alpha[64][4];
    int beg = g_offs[d];
    int cnt = g_offs[d + 1] - beg;
    int deg = cnt + 1;                    // + self loop
    float ad[4];
#pragma unroll
    for (int j = 0; j < 4; j++) ad[j] = g_ad1[d * 4 + j];

    float m[4] = { -3e38f, -3e38f, -3e38f, -3e38f };
    for (int i = tid; i < deg; i += 256) {
        int s = (i < cnt) ? g_srcs[beg + i] : d;
#pragma unroll
        for (int j = 0; j < 4; j++) {
            float e = g_as1[s * 4 + j] + ad[j];
            e = e > 0.f ? e : 0.2f * e;
            m[j] = fmaxf(m[j], e);
        }
    }
#pragma unroll
    for (int j = 0; j < 4; j++) m[j] = blk_max(m[j], wred, lane, wid);

    float ssum[4] = { 0.f, 0.f, 0.f, 0.f };
    for (int i = tid; i < deg; i += 256) {
        int s = (i < cnt) ? g_srcs[beg + i] : d;
#pragma unroll
        for (int j = 0; j < 4; j++) {
            float e = g_as1[s * 4 + j] + ad[j];
            e = e > 0.f ? e : 0.2f * e;
            ssum[j] += expf(e - m[j]);
        }
    }
    float inv[4];
#pragma unroll
    for (int j = 0; j < 4; j++) {
        float s2 = blk_sum(ssum[j], wred, lane, wid);
        inv[j] = 1.0f / (s2 + 1e-16f);
    }

    const __nv_bfloat162* hb = reinterpret_cast<const __nv_bfloat162*>(g_h1b);
    int h0 = tid >> 7;            // head of pair p1 = tid   (0/1)
    float a0x = 0.f, a0y = 0.f, a1x = 0.f, a1y = 0.f;
    for (int c0 = 0; c0 < deg; c0 += 64) {
        int chunk = min(64, deg - c0);
        __syncthreads();
        for (int t = tid; t < chunk * 4; t += 256) {
            int il = t >> 2, j = t & 3;
            int i = c0 + il;
            int s = (i < cnt) ? g_srcs[beg + i] : d;
            float e = g_as1[s * 4 + j] + ad[j];
            e = e > 0.f ? e : 0.2f * e;
            alpha[il][j] = expf(e - m[j]) * inv[j];
        }
        __syncthreads();
        for (int il = 0; il < chunk; il++) {
            int i = c0 + il;
            int s = (i < cnt) ? g_srcs[beg + i] : d;
            const __nv_bfloat162* row = hb + s * 512;
            float2 f0 = __bfloat1622float2(row[tid]);
            float2 f1 = __bfloat1622float2(row[tid + 256]);
            float a0 = alpha[il][h0];
            float a1 = alpha[il][h0 + 2];
            a0x += a0 * f0.x; a0y += a0 * f0.y;
            a1x += a1 * f1.x; a1y += a1 * f1.y;
        }
    }
    // epilogue: bias + ReLU, fp32 x1 for GEMM2
    int cp = (tid & 127) * 2;
    int off0 = h0 * 256 + cp;
    int off1 = (h0 + 2) * 256 + cp;
    float2 bb0 = *reinterpret_cast<const float2*>(&b1[off0]);
    float2 bb1 = *reinterpret_cast<const float2*>(&b1[off1]);
    float2 o0 = make_float2(fmaxf(a0x + bb0.x, 0.f), fmaxf(a0y + bb0.y, 0.f));
    float2 o1 = make_float2(fmaxf(a1x + bb1.x, 0.f), fmaxf(a1y + bb1.y, 0.f));
    *reinterpret_cast<float2*>(&g_x1[d * D1 + off0]) = o0;
    *reinterpret_cast<float2*>(&g_x1[d * D1 + off1]) = o1;
}

// ---------------- GEMM2: x1[N,1024] @ W2[1024,256] -> g_h2b (bf16) ------
// f32x2: row-pair accumulators (LDS.64 over As[k][row]) x dup-B smem.
#define BM 64
#define BN 128
#define KC 16
__global__ void k_gemm2(const float* __restrict__ W2) {
    __shared__ float As[KC][BM];       // [k][row], row pairs 8B-aligned
    __shared__ u64   Bdup[KC][BN];     // {w,w} per col
    int tid = threadIdx.x;
    int tx = tid & 31;                 // cols tx + 32j
    int ty = tid >> 5;                 // row pairs ty*2 + 16p
    int row0 = blockIdx.x * BM;
    int col0 = blockIdx.y * BN;
    u64 acc[4][4];
#pragma unroll
    for (int p = 0; p < 4; p++)
#pragma unroll
        for (int j = 0; j < 4; j++) acc[p][j] = 0ull;

    int arow = tid >> 2;               // A-fill: row this thread loads
    int akq  = tid & 3;                // which float4 of the KC chunk
    bool arow_ok = (row0 + arow) < NN;

    for (int kc = 0; kc < D1; kc += KC) {
        // fill A: 64 rows x 16 k, one float4 per thread
        float4 av = make_float4(0.f, 0.f, 0.f, 0.f);
        if (arow_ok)
            av = *reinterpret_cast<const float4*>(&g_x1[(row0 + arow) * D1 + kc + akq * 4]);
        As[akq * 4 + 0][arow] = av.x;
        As[akq * 4 + 1][arow] = av.y;
        As[akq * 4 + 2][arow] = av.z;
        As[akq * 4 + 3][arow] = av.w;
        // fill Bdup: 16 k x 128 cols
#pragma unroll
        for (int it = 0; it < 8; it++) {
            int e = tid + 256 * it;
            int k = e >> 7, c = e & 127;
            float w = W2[(kc + k) * HHID + col0 + c];
            Bdup[k][c] = pack2(w, w);
        }
        __syncthreads();
#pragma unroll
        for (int kk = 0; kk < KC; kk++) {
            u64 ap[4], bp[4];
#pragma unroll
            for (int p = 0; p < 4; p++)
                ap[p] = *reinterpret_cast<const u64*>(&As[kk][ty * 2 + 16 * p]);
#pragma unroll
            for (int j = 0; j < 4; j++)
                bp[j] = Bdup[kk][tx + 32 * j];
#pragma unroll
            for (int p = 0; p < 4; p++)
#pragma unroll
                for (int j = 0; j < 4; j++)
                    fma2(acc[p][j], ap[p], bp[j]);
        }
        __syncthreads();
    }
#pragma unroll
    for (int p = 0; p < 4; p++) {
        int r = row0 + ty * 2 + 16 * p;
        if (r + 1 < NN) {
#pragma unroll
            for (int j = 0; j < 4; j++) {
                float2 v = unpack2(acc[p][j]);
                int c = col0 + tx + 32 * j;
                g_h2b[r * HHID + c]       = __float2bfloat16(v.x);
                g_h2b[(r + 1) * HHID + c] = __float2bfloat16(v.y);
            }
        } else if (r < NN) {
#pragma unroll
            for (int j = 0; j < 4; j++) {
                float2 v = unpack2(acc[p][j]);
                g_h2b[r * HHID + col0 + tx + 32 * j] = __float2bfloat16(v.x);
            }
        }
    }
}

// ---------------- attention logits layer 2 (1 head, bf16 h2) ------------
__global__ void k_att2(const float* __restrict__ as, const float* __restrict__ adv) {
    int wid = threadIdx.x >> 5, lane = threadIdx.x & 31;
    int d = blockIdx.x * 4 + wid;
    if (d >= NN) return;
    const __nv_bfloat162* hb = reinterpret_cast<const __nv_bfloat162*>(g_h2b) + d * 128;
    const float2* as2 = reinterpret_cast<const float2*>(as);
    const float2* ad2 = reinterpret_cast<const float2*>(adv);
    float ps = 0.f, pd = 0.f;
#pragma unroll
    for (int t = 0; t < 4; t++) {
        int p = lane + 32 * t;
        float2 f = __bfloat1622float2(hb[p]);
        float2 a = as2[p], b = ad2[p];
        ps += f.x * a.x + f.y * a.y;
        pd += f.x * b.x + f.y * b.y;
    }
#pragma unroll
    for (int o = 16; o; o >>= 1) {
        ps += __shfl_xor_sync(0xffffffffu, ps, o);
        pd += __shfl_xor_sync(0xffffffffu, pd, o);
    }
    if (lane == 0) { g_as2[d] = ps; g_ad2[d] = pd; }
}

// ---------------- layer-2 aggregation + ReLU + mean pool (bf16 gather) --
__global__ void k_agg2(const float* __restrict__ b2) {
    int d = blockIdx.x, tid = threadIdx.x, lane = tid & 31, wid = tid >> 5;
    __shared__ float wred[8];
    __shared__ float alpha[256];
    int beg = g_offs[d], cnt = g_offs[d + 1] - beg, deg = cnt + 1;
    float ad = g_ad2[d];

    float m = -3e38f;
    for (int i = tid; i < deg; i += 256) {
        int s = (i < cnt) ? g_srcs[beg + i] : d;
        float e = g_as2[s] + ad; e = e > 0.f ? e : 0.2f * e;
        m = fmaxf(m, e);
    }
    m = blk_max(m, wred, lane, wid);

    float ss = 0.f;
    for (int i = tid; i < deg; i += 256) {
        int s = (i < cnt) ? g_srcs[beg + i] : d;
        float e = g_as2[s] + ad; e = e > 0.f ? e : 0.2f * e;
        ss += expf(e - m);
    }
    ss = blk_sum(ss, wred, lane, wid);
    float inv = 1.0f / (ss + 1e-16f);

    float acc = 0.f;
    for (int c0 = 0; c0 < deg; c0 += 256) {
        int chunk = min(256, deg - c0);
        __syncthreads();
        if (tid < chunk) {
            int i = c0 + tid;
            int s = (i < cnt) ? g_srcs[beg + i] : d;
            float e = g_as2[s] + ad; e = e > 0.f ? e : 0.2f * e;
            alpha[tid] = expf(e - m) * inv;
        }
        __syncthreads();
        for (int il = 0; il < chunk; il++) {
            int i = c0 + il;
            int s = (i < cnt) ? g_srcs[beg + i] : d;
            acc += alpha[il] * __bfloat162float(g_h2b[s * HHID + tid]);
        }
    }
    float v = acc + b2[tid];
    v = v > 0.f ? v : 0.f;                       // ReLU after layer 2
    atomicAdd(&g_pooled[tid], v * (1.0f / NN));  // mean pool
}

// ---------------- final MLP: gelu(pooled@Wv1+bv1)@Wv2+bv2 ----------------
__global__ void k_final(const float* __restrict__ Wv1, const float* __restrict__ bv1,
                        const float* __restrict__ Wv2, const float* __restrict__ bv2,
                        float* __restrict__ out) {
    __shared__ float sp[HHID];
    __shared__ float wred[4];
    int t = threadIdx.x;   // 128 threads
    for (int c = t; c < HHID; c += 128) sp[c] = g_pooled[c];
    __syncthreads();
    float a = 0.f;
    for (int k = 0; k < HHID; k++) a += sp[k] * Wv1[k * 128 + t];
    a += bv1[t];
    float g = a * normcdff(a);   // exact GELU
    float v = g * Wv2[t];
    int lane = t & 31, wid = t >> 5;
#pragma unroll
    for (int o = 16; o; o >>= 1) v += __shfl_xor_sync(0xffffffffu, v, o);
    if (lane == 0) wred[wid] = v;
    __syncthreads();
    if (t == 0) out[0] = wred[0] + wred[1] + wred[2] + wred[3] + bv2[0];
}

// ---------------- launch ----------------
extern "C" void kernel_launch(void* const* d_in, const int* in_sizes, int n_in,
                              void* d_out, int out_size) {
    const float* x       = (const float*)d_in[0];
    const int*   ei      = (const int*)  d_in[1];
    // d_in[2] edge_attr unused (GATConv built without edge_dim)
    const float* W1      = (const float*)d_in[3];
    const float* att_s1  = (const float*)d_in[4];
    const float* att_d1  = (const float*)d_in[5];
    const float* b1      = (const float*)d_in[6];
    const float* W2      = (const float*)d_in[7];
    const float* att_s2  = (const float*)d_in[8];
    const float* att_d2  = (const float*)d_in[9];
    const float* b2      = (const float*)d_in[10];
    const float* Wv1     = (const float*)d_in[11];
    const float* bv1     = (const float*)d_in[12];
    const float* Wv2     = (const float*)d_in[13];
    const float* bv2     = (const float*)d_in[14];
    float* out = (float*)d_out;

    k_zero<<<(NN + 255) / 256, 256>>>();
    k_hist<<<(EE + 255) / 256, 256>>>(ei);
    k_scan<<<1, 1024>>>();
    k_scatter<<<(EE + 255) / 256, 256>>>(ei);

    k_gemm1<<<NN / NPB, 256>>>(x, W1);
    k_att1<<<NN, 128>>>(att_s1, att_d1);
    k_agg1<<<NN, 256>>>(b1);

    dim3 g2((NN + BM - 1) / BM, HHID / BN);
    k_gemm2<<<g2, 256>>>(W2);
    k_att2<<<(NN + 3) / 4, 128>>>(att_s2, att_d2);
    k_agg2<<<NN, 256>>>(b2);

    k_final<<<1, 128>>>(Wv1, bv1, Wv2, bv2, out);
}

// round 8
// speedup vs baseline: 1.1520x; 1.0684x over previous
#include <cuda_runtime.h>
#include <cuda_bf16.h>
#include <math.h>
#include <stdint.h>

#define NN 10000
#define EE 160000
#define FIN 70
#define HHID 256
#define D1 1024   // HEADS*HID

typedef unsigned long long u64;

// ---------------- packed f32x2 helpers (sm_103a FFMA2) ----------------
__device__ __forceinline__ u64 pack2(float x, float y) {
    u64 r; asm("mov.b64 %0,{%1,%2};" : "=l"(r) : "f"(x), "f"(y)); return r;
}
__device__ __forceinline__ float2 unpack2(u64 v) {
    float2 f; asm("mov.b64 {%0,%1},%2;" : "=f"(f.x), "=f"(f.y) : "l"(v)); return f;
}
__device__ __forceinline__ void fma2(u64& c, u64 a, u64 b) {
    asm("fma.rn.f32x2 %0,%1,%2,%0;" : "+l"(c) : "l"(a), "l"(b));
}

// ---------------- device scratch (no allocations allowed) ----------------
__device__ __align__(16) __nv_bfloat16 g_h1b[NN * D1];  // layer-1 linear out (bf16)
__device__ __align__(16) __nv_bfloat16 g_x1b[NN * D1];  // relu(agg1+b1) bf16 (GEMM2 A)
__device__ __align__(16) float g_as1[NN * 4];
__device__ __align__(16) float g_ad1[NN * 4];
__device__ __align__(16) float g_h2[NN * HHID];         // layer-2 linear out (fp32)
__device__ float g_as2[NN];
__device__ float g_ad2[NN];
__device__ __align__(16) float g_ex1[EE * 4];           // exp(leaky(e)) per edge, layer1
__device__ float g_ex2[EE];                             // layer2
__device__ __align__(16) float g_exself1[NN * 4];
__device__ __align__(16) float g_den1[NN * 4];
__device__ float g_exself2[NN];
__device__ float g_den2[NN];
__device__ float g_pooled[HHID];
__device__ int   g_deg[NN];
__device__ int   g_offs[NN + 1];
__device__ int   g_cursor[NN];
__device__ int   g_srcs[EE];
__device__ int   g_eid[EE];

// ---------------- small utils ----------------
__global__ void k_zero() {
    int i = blockIdx.x * blockDim.x + threadIdx.x;
    if (i < NN)  g_deg[i] = 0;
    if (i < HHID) g_pooled[i] = 0.f;
}

__global__ void k_hist(const int* __restrict__ ei) {
    int i = blockIdx.x * blockDim.x + threadIdx.x;
    if (i < EE) atomicAdd(&g_deg[ei[EE + i]], 1);
}

__global__ void k_scan() {
    __shared__ int sbuf[1024];
    int t = threadIdx.x;
    int base = t * 10;
    int loc[10];
    int sum = 0;
#pragma unroll
    for (int q = 0; q < 10; q++) {
        int idx = base + q;
        int v = (idx < NN) ? g_deg[idx] : 0;
        loc[q] = sum; sum += v;
    }
    sbuf[t] = sum;
    __syncthreads();
    for (int off = 1; off < 1024; off <<= 1) {
        int tmp = (t >= off) ? sbuf[t - off] : 0;
        __syncthreads();
        sbuf[t] += tmp;
        __syncthreads();
    }
    int excl = sbuf[t] - sum;
#pragma unroll
    for (int q = 0; q < 10; q++) {
        int idx = base + q;
        if (idx < NN) { int o = excl + loc[q]; g_offs[idx] = o; g_cursor[idx] = o; }
    }
    if (t == 1023) g_offs[NN] = sbuf[1023];
}

__global__ void k_scatter(const int* __restrict__ ei) {
    int i = blockIdx.x * blockDim.x + threadIdx.x;
    if (i < EE) {
        int dnode = ei[EE + i];
        int pos = atomicAdd(&g_cursor[dnode], 1);
        g_srcs[pos] = ei[i];
        g_eid[pos] = i;
    }
}

// ---------------- GEMM1: x[N,70] @ W1[70,1024] -> g_h1b (bf16) ----------
// 32 nodes/block (16 node-pairs, f32x2 acc), head-pair per blockIdx.y.
#define NPB 32
__global__ void __launch_bounds__(256) k_gemm1(const float* __restrict__ x,
                                               const float* __restrict__ W1) {
    __shared__ __align__(16) float xs[FIN][NPB];
    int tid = threadIdx.x;
    int n0 = blockIdx.x * NPB;
    int hp = blockIdx.y;               // 0/1: cols hp*512 + {0,256} + tid
    for (int i = tid; i < NPB * FIN; i += 256) {
        int n = i / FIN, k = i - n * FIN;
        xs[k][n] = (n0 + n < NN) ? x[(n0 + n) * FIN + k] : 0.f;
    }
    __syncthreads();
    u64 acc[16][2];
#pragma unroll
    for (int p = 0; p < 16; p++) { acc[p][0] = 0ull; acc[p][1] = 0ull; }

    for (int k = 0; k < FIN; k++) {
        u64 wd[2];
#pragma unroll
        for (int j = 0; j < 2; j++) {
            float w = W1[k * D1 + hp * 512 + j * 256 + tid];
            wd[j] = pack2(w, w);
        }
#pragma unroll
        for (int p = 0; p < 16; p++) {
            u64 xp = *reinterpret_cast<const u64*>(&xs[k][2 * p]);
            fma2(acc[p][0], xp, wd[0]);
            fma2(acc[p][1], xp, wd[1]);
        }
    }
#pragma unroll
    for (int p = 0; p < 16; p++) {
        int r0 = n0 + 2 * p;
        if (r0 >= NN) break;
#pragma unroll
        for (int j = 0; j < 2; j++) {
            float2 v = unpack2(acc[p][j]);
            int c = hp * 512 + j * 256 + tid;
            g_h1b[(size_t)r0 * D1 + c] = __float2bfloat16(v.x);
            if (r0 + 1 < NN)
                g_h1b[(size_t)(r0 + 1) * D1 + c] = __float2bfloat16(v.y);
        }
    }
}

// ---------------- attention logits layer 1 + self-loop ex + den init ---
__global__ void k_att1(const float* __restrict__ as, const float* __restrict__ adv) {
    int wid = threadIdx.x >> 5, lane = threadIdx.x & 31;
    int d = blockIdx.x;
    const __nv_bfloat162* hb = reinterpret_cast<const __nv_bfloat162*>(g_h1b) + (size_t)d * 512 + wid * 128;
    const float2* as2 = reinterpret_cast<const float2*>(as)  + wid * 128;
    const float2* ad2 = reinterpret_cast<const float2*>(adv) + wid * 128;
    float ps = 0.f, pd = 0.f;
#pragma unroll
    for (int t = 0; t < 4; t++) {
        int p = lane + 32 * t;
        float2 f = __bfloat1622float2(hb[p]);
        float2 a = as2[p], b = ad2[p];
        ps += f.x * a.x + f.y * a.y;
        pd += f.x * b.x + f.y * b.y;
    }
#pragma unroll
    for (int o = 16; o; o >>= 1) {
        ps += __shfl_xor_sync(0xffffffffu, ps, o);
        pd += __shfl_xor_sync(0xffffffffu, pd, o);
    }
    if (lane == 0) {
        g_as1[d * 4 + wid] = ps; g_ad1[d * 4 + wid] = pd;
        float e = ps + pd;                    // self-loop logit
        e = e > 0.f ? e : 0.2f * e;
        float ex = expf(e);
        g_exself1[d * 4 + wid] = ex;
        g_den1[d * 4 + wid] = ex;             // denominator init
    }
}

// ---------------- edge kernel layer 1: ex + denom atomics --------------
__global__ void k_edge1(const int* __restrict__ ei) {
    int i = blockIdx.x * blockDim.x + threadIdx.x;
    if (i >= EE) return;
    int s = ei[i], d = ei[EE + i];
    float4 a = *reinterpret_cast<const float4*>(&g_as1[s * 4]);
    float4 b = *reinterpret_cast<const float4*>(&g_ad1[d * 4]);
    float e0 = a.x + b.x; e0 = e0 > 0.f ? e0 : 0.2f * e0; e0 = expf(e0);
    float e1 = a.y + b.y; e1 = e1 > 0.f ? e1 : 0.2f * e1; e1 = expf(e1);
    float e2 = a.z + b.z; e2 = e2 > 0.f ? e2 : 0.2f * e2; e2 = expf(e2);
    float e3 = a.w + b.w; e3 = e3 > 0.f ? e3 : 0.2f * e3; e3 = expf(e3);
    *reinterpret_cast<float4*>(&g_ex1[(size_t)i * 4]) = make_float4(e0, e1, e2, e3);
    atomicAdd(&g_den1[d * 4 + 0], e0);
    atomicAdd(&g_den1[d * 4 + 1], e1);
    atomicAdd(&g_den1[d * 4 + 2], e2);
    atomicAdd(&g_den1[d * 4 + 3], e3);
}

// ---------------- layer-1 aggregation: single pass, no barriers --------
// thread tid handles bf162-pairs tid (head h0) and tid+256 (head h0+2)
__global__ void k_agg1(const float* __restrict__ b1) {
    int d = blockIdx.x, tid = threadIdx.x;
    int beg = g_offs[d], cnt = g_offs[d + 1] - beg;
    int h0 = tid >> 7;
    const __nv_bfloat162* hb = reinterpret_cast<const __nv_bfloat162*>(g_h1b);

    // self-loop term
    float ex0 = g_exself1[d * 4 + h0];
    float ex1 = g_exself1[d * 4 + h0 + 2];
    const __nv_bfloat162* rowd = hb + (size_t)d * 512;
    float2 f0 = __bfloat1622float2(rowd[tid]);
    float2 f1 = __bfloat1622float2(rowd[tid + 256]);
    float a0x = ex0 * f0.x, a0y = ex0 * f0.y;
    float a1x = ex1 * f1.x, a1y = ex1 * f1.y;

#pragma unroll 2
    for (int i = 0; i < cnt; i++) {
        int s   = g_srcs[beg + i];
        int eid = g_eid[beg + i];
        float e0 = g_ex1[(size_t)eid * 4 + h0];
        float e1 = g_ex1[(size_t)eid * 4 + h0 + 2];
        const __nv_bfloat162* r2 = hb + (size_t)s * 512;
        float2 g0 = __bfloat1622float2(r2[tid]);
        float2 g1 = __bfloat1622float2(r2[tid + 256]);
        a0x += e0 * g0.x; a0y += e0 * g0.y;
        a1x += e1 * g1.x; a1y += e1 * g1.y;
    }

    float inv0 = 1.f / (g_den1[d * 4 + h0] + 1e-16f);
    float inv1 = 1.f / (g_den1[d * 4 + h0 + 2] + 1e-16f);
    int cp = (tid & 127) * 2;
    int off0 = h0 * 256 + cp;
    int off1 = (h0 + 2) * 256 + cp;
    float2 bb0 = *reinterpret_cast<const float2*>(&b1[off0]);
    float2 bb1 = *reinterpret_cast<const float2*>(&b1[off1]);
    __nv_bfloat162* xout = reinterpret_cast<__nv_bfloat162*>(g_x1b + (size_t)d * D1);
    xout[off0 >> 1] = __floats2bfloat162_rn(fmaxf(a0x * inv0 + bb0.x, 0.f),
                                            fmaxf(a0y * inv0 + bb0.y, 0.f));
    xout[off1 >> 1] = __floats2bfloat162_rn(fmaxf(a1x * inv1 + bb1.x, 0.f),
                                            fmaxf(a1y * inv1 + bb1.y, 0.f));
}

// ---------------- GEMM2: x1b[N,1024](bf16) @ W2[1024,256] -> g_h2 fp32 --
// FFMA2, fma-pipe-bound layout: A broadcast+dup, B native u64 col-pairs.
#define G2_BM 32
#define G2_BN 256
#define G2_KC 16
__global__ void __launch_bounds__(256) k_gemm2(const float* __restrict__ W2) {
    __shared__ float As[G2_KC][G2_BM];
    __shared__ __align__(16) float Bs[G2_KC][G2_BN];
    int tid = threadIdx.x, tx = tid & 31, ty = tid >> 5;
    int row0 = blockIdx.x * G2_BM;
    u64 acc[4][4];
#pragma unroll
    for (int r = 0; r < 4; r++)
#pragma unroll
        for (int p = 0; p < 4; p++) acc[r][p] = 0ull;

    int ar = tid >> 2, akq = tid & 3;          // A fill: tid<128 only
    bool arok = (tid < 128) && (row0 + ar < NN);

    // prefetch chunk 0
    u64 pa = 0ull;
    if (arok) pa = *reinterpret_cast<const u64*>(&g_x1b[(size_t)(row0 + ar) * D1 + akq * 4]);
    float4 pb[4];
#pragma unroll
    for (int q = 0; q < 4; q++) {
        int i = tid + 256 * q;
        int kk = i >> 6, c4 = (i & 63) * 4;
        pb[q] = *reinterpret_cast<const float4*>(&W2[(size_t)kk * HHID + c4]);
    }

    for (int kc = 0; kc < D1; kc += G2_KC) {
        // store staged chunk
        if (tid < 128) {
            __nv_bfloat162 b01 = reinterpret_cast<__nv_bfloat162*>(&pa)[0];
            __nv_bfloat162 b23 = reinterpret_cast<__nv_bfloat162*>(&pa)[1];
            float2 f01 = __bfloat1622float2(b01);
            float2 f23 = __bfloat1622float2(b23);
            As[akq * 4 + 0][ar] = f01.x;
            As[akq * 4 + 1][ar] = f01.y;
            As[akq * 4 + 2][ar] = f23.x;
            As[akq * 4 + 3][ar] = f23.y;
        }
#pragma unroll
        for (int q = 0; q < 4; q++) {
            int i = tid + 256 * q;
            int kk = i >> 6, c4 = (i & 63) * 4;
            *reinterpret_cast<float4*>(&Bs[kk][c4]) = pb[q];
        }
        __syncthreads();
        // prefetch next chunk
        if (kc + G2_KC < D1) {
            if (arok)
                pa = *reinterpret_cast<const u64*>(&g_x1b[(size_t)(row0 + ar) * D1 + kc + G2_KC + akq * 4]);
#pragma unroll
            for (int q = 0; q < 4; q++) {
                int i = tid + 256 * q;
                int kk = i >> 6, c4 = (i & 63) * 4;
                pb[q] = *reinterpret_cast<const float4*>(&W2[(size_t)(kc + G2_KC + kk) * HHID + c4]);
            }
        }
        // compute
#pragma unroll
        for (int kk = 0; kk < G2_KC; kk++) {
            u64 ad_[4], b_[4];
#pragma unroll
            for (int r = 0; r < 4; r++) {
                float a = As[kk][ty + 8 * r];         // warp-uniform broadcast
                ad_[r] = pack2(a, a);
            }
#pragma unroll
            for (int p = 0; p < 4; p++)
                b_[p] = *reinterpret_cast<const u64*>(&Bs[kk][2 * (tx + 32 * p)]);
#pragma unroll
            for (int r = 0; r < 4; r++)
#pragma unroll
                for (int p = 0; p < 4; p++)
                    fma2(acc[r][p], ad_[r], b_[p]);
        }
        __syncthreads();
    }
#pragma unroll
    for (int r = 0; r < 4; r++) {
        int row = row0 + ty + 8 * r;
        if (row < NN) {
#pragma unroll
            for (int p = 0; p < 4; p++) {
                float2 v = unpack2(acc[r][p]);
                *reinterpret_cast<float2*>(&g_h2[(size_t)row * HHID + 2 * (tx + 32 * p)]) =
                    make_float2(v.x, v.y);
            }
        }
    }
}

// ---------------- attention logits layer 2 + self ex + den init --------
__global__ void k_att2(const float* __restrict__ as, const float* __restrict__ adv) {
    int wid = threadIdx.x >> 5, lane = threadIdx.x & 31;
    int d = blockIdx.x * 4 + wid;
    if (d >= NN) return;
    const float4* h4  = reinterpret_cast<const float4*>(g_h2 + (size_t)d * HHID);
    const float4* as4 = reinterpret_cast<const float4*>(as);
    const float4* ad4 = reinterpret_cast<const float4*>(adv);
    float ps = 0.f, pd = 0.f;
#pragma unroll
    for (int t = 0; t < 2; t++) {
        int p = lane + 32 * t;
        float4 f = h4[p];
        float4 a = as4[p], b = ad4[p];
        ps += f.x * a.x + f.y * a.y + f.z * a.z + f.w * a.w;
        pd += f.x * b.x + f.y * b.y + f.z * b.z + f.w * b.w;
    }
#pragma unroll
    for (int o = 16; o; o >>= 1) {
        ps += __shfl_xor_sync(0xffffffffu, ps, o);
        pd += __shfl_xor_sync(0xffffffffu, pd, o);
    }
    if (lane == 0) {
        g_as2[d] = ps; g_ad2[d] = pd;
        float e = ps + pd;
        e = e > 0.f ? e : 0.2f * e;
        float ex = expf(e);
        g_exself2[d] = ex;
        g_den2[d] = ex;
    }
}

// ---------------- edge kernel layer 2 ----------------------------------
__global__ void k_edge2(const int* __restrict__ ei) {
    int i = blockIdx.x * blockDim.x + threadIdx.x;
    if (i >= EE) return;
    int s = ei[i], d = ei[EE + i];
    float e = g_as2[s] + g_ad2[d];
    e = e > 0.f ? e : 0.2f * e;
    float ex = expf(e);
    g_ex2[i] = ex;
    atomicAdd(&g_den2[d], ex);
}

// ---------------- layer-2 aggregation + ReLU + mean pool ---------------
__global__ void k_agg2(const float* __restrict__ b2) {
    int d = blockIdx.x, tid = threadIdx.x;
    int beg = g_offs[d], cnt = g_offs[d + 1] - beg;
    float acc = g_exself2[d] * g_h2[(size_t)d * HHID + tid];
#pragma unroll 2
    for (int i = 0; i < cnt; i++) {
        int s   = g_srcs[beg + i];
        int eid = g_eid[beg + i];
        acc += g_ex2[eid] * g_h2[(size_t)s * HHID + tid];
    }
    float inv = 1.f / (g_den2[d] + 1e-16f);
    float v = acc * inv + b2[tid];
    v = v > 0.f ? v : 0.f;
    atomicAdd(&g_pooled[tid], v * (1.0f / NN));
}

// ---------------- final MLP ----------------
__global__ void k_final(const float* __restrict__ Wv1, const float* __restrict__ bv1,
                        const float* __restrict__ Wv2, const float* __restrict__ bv2,
                        float* __restrict__ out) {
    __shared__ float sp[HHID];
    __shared__ float wred[4];
    int t = threadIdx.x;   // 128 threads
    for (int c = t; c < HHID; c += 128) sp[c] = g_pooled[c];
    __syncthreads();
    float a = 0.f;
    for (int k = 0; k < HHID; k++) a += sp[k] * Wv1[k * 128 + t];
    a += bv1[t];
    float g = a * normcdff(a);
    float v = g * Wv2[t];
    int lane = t & 31, wid = t >> 5;
#pragma unroll
    for (int o = 16; o; o >>= 1) v += __shfl_xor_sync(0xffffffffu, v, o);
    if (lane == 0) wred[wid] = v;
    __syncthreads();
    if (t == 0) out[0] = wred[0] + wred[1] + wred[2] + wred[3] + bv2[0];
}

// ---------------- launch ----------------
extern "C" void kernel_launch(void* const* d_in, const int* in_sizes, int n_in,
                              void* d_out, int out_size) {
    const float* x       = (const float*)d_in[0];
    const int*   ei      = (const int*)  d_in[1];
    // d_in[2] edge_attr unused (GATConv built without edge_dim)
    const float* W1      = (const float*)d_in[3];
    const float* att_s1  = (const float*)d_in[4];
    const float* att_d1  = (const float*)d_in[5];
    const float* b1      = (const float*)d_in[6];
    const float* W2      = (const float*)d_in[7];
    const float* att_s2  = (const float*)d_in[8];
    const float* att_d2  = (const float*)d_in[9];
    const float* b2      = (const float*)d_in[10];
    const float* Wv1     = (const float*)d_in[11];
    const float* bv1     = (const float*)d_in[12];
    const float* Wv2     = (const float*)d_in[13];
    const float* bv2     = (const float*)d_in[14];
    float* out = (float*)d_out;

    k_zero<<<(NN + 255) / 256, 256>>>();
    k_hist<<<(EE + 255) / 256, 256>>>(ei);
    k_scan<<<1, 1024>>>();
    k_scatter<<<(EE + 255) / 256, 256>>>(ei);

    dim3 g1((NN + NPB - 1) / NPB, 2);
    k_gemm1<<<g1, 256>>>(x, W1);
    k_att1<<<NN, 128>>>(att_s1, att_d1);
    k_edge1<<<(EE + 255) / 256, 256>>>(ei);
    k_agg1<<<NN, 256>>>(b1);

    k_gemm2<<<(NN + G2_BM - 1) / G2_BM, 256>>>(W2);
    k_att2<<<(NN + 3) / 4, 128>>>(att_s2, att_d2);
    k_edge2<<<(EE + 255) / 256, 256>>>(ei);
    k_agg2<<<NN, 256>>>(b2);

    k_final<<<1, 128>>>(Wv1, bv1, Wv2, bv2, out);
}

// round 10
// speedup vs baseline: 1.8838x; 1.6352x over previous
#include <cuda_runtime.h>
#include <cuda_bf16.h>
#include <math.h>
#include <stdint.h>

#define NN 10000
#define EE 160000
#define FIN 70
#define HHID 256
#define D1 1024   // HEADS*HID

typedef unsigned long long u64;

// ---------------- packed f32x2 helpers (sm_103a FFMA2) ----------------
__device__ __forceinline__ u64 pack2(float x, float y) {
    u64 r; asm("mov.b64 %0,{%1,%2};" : "=l"(r) : "f"(x), "f"(y)); return r;
}
__device__ __forceinline__ float2 unpack2(u64 v) {
    float2 f; asm("mov.b64 {%0,%1},%2;" : "=f"(f.x), "=f"(f.y) : "l"(v)); return f;
}
__device__ __forceinline__ void fma2(u64& c, u64 a, u64 b) {
    asm("fma.rn.f32x2 %0,%1,%2,%0;" : "+l"(c) : "l"(a), "l"(b));
}
__device__ __forceinline__ uint32_t smem_u32(const void* p) {
    uint32_t a;
    asm("{ .reg .u64 t; cvta.to.shared.u64 t, %1; cvt.u32.u64 %0, t; }" : "=r"(a) : "l"(p));
    return a;
}
__device__ __forceinline__ float4 bf4_to_f4(u64 v) {
    __nv_bfloat162 lo = reinterpret_cast<__nv_bfloat162*>(&v)[0];
    __nv_bfloat162 hi = reinterpret_cast<__nv_bfloat162*>(&v)[1];
    float2 a = __bfloat1622float2(lo), b = __bfloat1622float2(hi);
    return make_float4(a.x, a.y, b.x, b.y);
}

// ---------------- device scratch (no allocations allowed) ----------------
__device__ __align__(16) __nv_bfloat16 g_h1b[NN * D1];  // layer-1 linear out (bf16)
__device__ __align__(16) __nv_bfloat16 g_x1b[NN * D1];  // relu(agg1+b1) bf16 (GEMM2 A)
__device__ __align__(16) __nv_bfloat16 g_w2b[HHID * D1];// W2^T bf16 [n][k], k contiguous
__device__ __align__(16) float g_as1[NN * 4];
__device__ __align__(16) float g_ad1[NN * 4];
__device__ __align__(16) float g_h2[NN * HHID];         // layer-2 linear out (fp32)
__device__ float g_as2[NN];
__device__ float g_ad2[NN];
__device__ __align__(16) float g_ex1s[EE * 4];          // exp(leaky) per edge, DST-SORTED
__device__ float g_ex2s[EE];
__device__ __align__(16) float g_exself1[NN * 4];
__device__ __align__(16) float g_den1[NN * 4];
__device__ float g_exself2[NN];
__device__ float g_den2[NN];
__device__ float g_pooled[HHID];
__device__ int   g_deg[NN];
__device__ int   g_offs[NN + 1];
__device__ int   g_cursor[NN];
__device__ int   g_srcs[EE];
__device__ int   g_pos[EE];      // original edge -> sorted slot

// ---------------- small utils ----------------
__global__ void k_zero() {
    int i = blockIdx.x * blockDim.x + threadIdx.x;
    if (i < NN)  g_deg[i] = 0;
    if (i < HHID) g_pooled[i] = 0.f;
}

__global__ void k_hist(const int* __restrict__ ei) {
    int i = blockIdx.x * blockDim.x + threadIdx.x;
    if (i < EE) atomicAdd(&g_deg[ei[EE + i]], 1);
}

__global__ void k_scan() {
    __shared__ int sbuf[1024];
    int t = threadIdx.x;
    int base = t * 10;
    int loc[10];
    int sum = 0;
#pragma unroll
    for (int q = 0; q < 10; q++) {
        int idx = base + q;
        int v = (idx < NN) ? g_deg[idx] : 0;
        loc[q] = sum; sum += v;
    }
    sbuf[t] = sum;
    __syncthreads();
    for (int off = 1; off < 1024; off <<= 1) {
        int tmp = (t >= off) ? sbuf[t - off] : 0;
        __syncthreads();
        sbuf[t] += tmp;
        __syncthreads();
    }
    int excl = sbuf[t] - sum;
#pragma unroll
    for (int q = 0; q < 10; q++) {
        int idx = base + q;
        if (idx < NN) { int o = excl + loc[q]; g_offs[idx] = o; g_cursor[idx] = o; }
    }
    if (t == 1023) g_offs[NN] = sbuf[1023];
}

__global__ void k_scatter(const int* __restrict__ ei) {
    int i = blockIdx.x * blockDim.x + threadIdx.x;
    if (i < EE) {
        int dnode = ei[EE + i];
        int pos = atomicAdd(&g_cursor[dnode], 1);
        g_srcs[pos] = ei[i];
        g_pos[i] = pos;
    }
}

// ---------------- W2 [1024,256] fp32 -> g_w2b [256][1024] bf16 ----------
__global__ void k_prepW2(const float* __restrict__ W2) {
    __shared__ float t[32][33];
    int k0 = blockIdx.x * 32, n0 = blockIdx.y * 32;
    int tx = threadIdx.x & 31, ty = threadIdx.x >> 5;   // 256 threads
#pragma unroll
    for (int i = 0; i < 4; i++)
        t[ty + 8 * i][tx] = W2[(k0 + ty + 8 * i) * HHID + n0 + tx];
    __syncthreads();
#pragma unroll
    for (int i = 0; i < 4; i++)
        g_w2b[(size_t)(n0 + ty + 8 * i) * D1 + k0 + tx] = __float2bfloat16(t[tx][ty + 8 * i]);
}

// ---------------- GEMM1: x[N,70] @ W1[70,1024] -> g_h1b (bf16) ----------
#define NPB 32
__global__ void __launch_bounds__(256) k_gemm1(const float* __restrict__ x,
                                               const float* __restrict__ W1) {
    __shared__ __align__(16) float xs[FIN][NPB];
    int tid = threadIdx.x;
    int n0 = blockIdx.x * NPB;
    int hp = blockIdx.y;               // 0/1: cols hp*512 + {0,256} + tid
    for (int i = tid; i < NPB * FIN; i += 256) {
        int n = i / FIN, k = i - n * FIN;
        xs[k][n] = (n0 + n < NN) ? x[(n0 + n) * FIN + k] : 0.f;
    }
    __syncthreads();
    u64 acc[16][2];
#pragma unroll
    for (int p = 0; p < 16; p++) { acc[p][0] = 0ull; acc[p][1] = 0ull; }

    for (int k = 0; k < FIN; k++) {
        u64 wd[2];
#pragma unroll
        for (int j = 0; j < 2; j++) {
            float w = W1[k * D1 + hp * 512 + j * 256 + tid];
            wd[j] = pack2(w, w);
        }
#pragma unroll
        for (int p = 0; p < 16; p++) {
            u64 xp = *reinterpret_cast<const u64*>(&xs[k][2 * p]);
            fma2(acc[p][0], xp, wd[0]);
            fma2(acc[p][1], xp, wd[1]);
        }
    }
#pragma unroll
    for (int p = 0; p < 16; p++) {
        int r0 = n0 + 2 * p;
        if (r0 >= NN) break;
#pragma unroll
        for (int j = 0; j < 2; j++) {
            float2 v = unpack2(acc[p][j]);
            int c = hp * 512 + j * 256 + tid;
            g_h1b[(size_t)r0 * D1 + c] = __float2bfloat16(v.x);
            if (r0 + 1 < NN)
                g_h1b[(size_t)(r0 + 1) * D1 + c] = __float2bfloat16(v.y);
        }
    }
}

// ---------------- attention logits layer 1 + self-loop ex + den init ---
__global__ void k_att1(const float* __restrict__ as, const float* __restrict__ adv) {
    int wid = threadIdx.x >> 5, lane = threadIdx.x & 31;
    int d = blockIdx.x;
    const u64* hb = reinterpret_cast<const u64*>(g_h1b + (size_t)d * D1 + wid * 256);
    const float4* as4 = reinterpret_cast<const float4*>(as  + wid * 256);
    const float4* ad4 = reinterpret_cast<const float4*>(adv + wid * 256);
    float ps = 0.f, pd = 0.f;
#pragma unroll
    for (int t = 0; t < 2; t++) {
        int p = lane + 32 * t;
        float4 f = bf4_to_f4(hb[p]);
        float4 a = as4[p], b = ad4[p];
        ps += f.x * a.x + f.y * a.y + f.z * a.z + f.w * a.w;
        pd += f.x * b.x + f.y * b.y + f.z * b.z + f.w * b.w;
    }
#pragma unroll
    for (int o = 16; o; o >>= 1) {
        ps += __shfl_xor_sync(0xffffffffu, ps, o);
        pd += __shfl_xor_sync(0xffffffffu, pd, o);
    }
    if (lane == 0) {
        g_as1[d * 4 + wid] = ps; g_ad1[d * 4 + wid] = pd;
        float e = ps + pd;
        e = e > 0.f ? e : 0.2f * e;
        float ex = expf(e);
        g_exself1[d * 4 + wid] = ex;
        g_den1[d * 4 + wid] = ex;
    }
}

// ---------------- edge kernel layer 1: ex (sorted) + denom atomics -----
__global__ void k_edge1(const int* __restrict__ ei) {
    int i = blockIdx.x * blockDim.x + threadIdx.x;
    if (i >= EE) return;
    int s = ei[i], d = ei[EE + i];
    float4 a = *reinterpret_cast<const float4*>(&g_as1[s * 4]);
    float4 b = *reinterpret_cast<const float4*>(&g_ad1[d * 4]);
    float e0 = a.x + b.x; e0 = e0 > 0.f ? e0 : 0.2f * e0; e0 = expf(e0);
    float e1 = a.y + b.y; e1 = e1 > 0.f ? e1 : 0.2f * e1; e1 = expf(e1);
    float e2 = a.z + b.z; e2 = e2 > 0.f ? e2 : 0.2f * e2; e2 = expf(e2);
    float e3 = a.w + b.w; e3 = e3 > 0.f ? e3 : 0.2f * e3; e3 = expf(e3);
    int pos = g_pos[i];
    *reinterpret_cast<float4*>(&g_ex1s[(size_t)pos * 4]) = make_float4(e0, e1, e2, e3);
    atomicAdd(&g_den1[d * 4 + 0], e0);
    atomicAdd(&g_den1[d * 4 + 1], e1);
    atomicAdd(&g_den1[d * 4 + 2], e2);
    atomicAdd(&g_den1[d * 4 + 3], e3);
}

// ---------------- layer-1 aggregation: single pass, vectorized ---------
// thread t handles channels [4t, 4t+4) -> one head per thread (h = t>>6)
__global__ void k_agg1(const float* __restrict__ b1) {
    int d = blockIdx.x, t = threadIdx.x;
    int beg = g_offs[d], cnt = g_offs[d + 1] - beg;
    int h = t >> 6;
    const u64* hb = reinterpret_cast<const u64*>(g_h1b);

    // self-loop term
    float ex = g_exself1[d * 4 + h];
    float4 f = bf4_to_f4(hb[(size_t)d * 256 + t]);
    float ax = ex * f.x, ay = ex * f.y, az = ex * f.z, aw = ex * f.w;

#pragma unroll 4
    for (int i = 0; i < cnt; i++) {
        int s = g_srcs[beg + i];
        float e = g_ex1s[(size_t)(beg + i) * 4 + h];
        float4 g = bf4_to_f4(hb[(size_t)s * 256 + t]);
        ax += e * g.x; ay += e * g.y; az += e * g.z; aw += e * g.w;
    }

    float inv = 1.f / (g_den1[d * 4 + h] + 1e-16f);
    float4 bb = *reinterpret_cast<const float4*>(&b1[4 * t]);
    __nv_bfloat162 lo = __floats2bfloat162_rn(fmaxf(ax * inv + bb.x, 0.f),
                                              fmaxf(ay * inv + bb.y, 0.f));
    __nv_bfloat162 hi = __floats2bfloat162_rn(fmaxf(az * inv + bb.z, 0.f),
                                              fmaxf(aw * inv + bb.w, 0.f));
    u64 outv;
    reinterpret_cast<__nv_bfloat162*>(&outv)[0] = lo;
    reinterpret_cast<__nv_bfloat162*>(&outv)[1] = hi;
    *reinterpret_cast<u64*>(&g_x1b[(size_t)d * D1 + 4 * t]) = outv;
}

// ---------------- GEMM2 via mma.sync (HMMA bf16) ------------------------
// x1b[N,1024](bf16, row-major A) @ W2 -> g_h2 fp32. B = g_w2b[n][k].
#define MM_BM 128
#define MM_BN 128
#define MM_BK 32
#define MM_LDS 40      // row stride in halves (32 + 8 pad): conflict-free ldmatrix
__global__ void __launch_bounds__(256) k_gemm2(int dummy) {
    __shared__ __align__(16) __nv_bfloat16 As[MM_BM][MM_LDS];
    __shared__ __align__(16) __nv_bfloat16 Bs[MM_BN][MM_LDS];
    int tid = threadIdx.x, lane = tid & 31, w = tid >> 5;
    int wm = w >> 2, wn = w & 3;                 // warp tile: 64m x 32n
    int row0 = blockIdx.x * MM_BM;
    int col0 = blockIdx.y * MM_BN;

    float acc[4][4][4];
#pragma unroll
    for (int i = 0; i < 4; i++)
#pragma unroll
        for (int j = 0; j < 4; j++)
#pragma unroll
            for (int q = 0; q < 4; q++) acc[i][j][q] = 0.f;

    // global-load slots: 512 x 16B for each of A,B; 2 per thread
    int rA0 = (tid + 0)   >> 2, qA0 = (tid + 0)   & 3;
    int rA1 = (tid + 256) >> 2, qA1 = (tid + 256) & 3;

    uint4 pa0, pa1, pb0, pb1;
    {
        pa0 = make_uint4(0, 0, 0, 0); pa1 = make_uint4(0, 0, 0, 0);
        if (row0 + rA0 < NN)
            pa0 = *reinterpret_cast<const uint4*>(&g_x1b[(size_t)(row0 + rA0) * D1 + qA0 * 8]);
        if (row0 + rA1 < NN)
            pa1 = *reinterpret_cast<const uint4*>(&g_x1b[(size_t)(row0 + rA1) * D1 + qA1 * 8]);
        pb0 = *reinterpret_cast<const uint4*>(&g_w2b[(size_t)(col0 + rA0) * D1 + qA0 * 8]);
        pb1 = *reinterpret_cast<const uint4*>(&g_w2b[(size_t)(col0 + rA1) * D1 + qA1 * 8]);
    }

    for (int kc = 0; kc < D1; kc += MM_BK) {
        *reinterpret_cast<uint4*>(&As[rA0][qA0 * 8]) = pa0;
        *reinterpret_cast<uint4*>(&As[rA1][qA1 * 8]) = pa1;
        *reinterpret_cast<uint4*>(&Bs[rA0][qA0 * 8]) = pb0;
        *reinterpret_cast<uint4*>(&Bs[rA1][qA1 * 8]) = pb1;
        __syncthreads();

        if (kc + MM_BK < D1) {
            int kn = kc + MM_BK;
            pa0 = make_uint4(0, 0, 0, 0); pa1 = make_uint4(0, 0, 0, 0);
            if (row0 + rA0 < NN)
                pa0 = *reinterpret_cast<const uint4*>(&g_x1b[(size_t)(row0 + rA0) * D1 + kn + qA0 * 8]);
            if (row0 + rA1 < NN)
                pa1 = *reinterpret_cast<const uint4*>(&g_x1b[(size_t)(row0 + rA1) * D1 + kn + qA1 * 8]);
            pb0 = *reinterpret_cast<const uint4*>(&g_w2b[(size_t)(col0 + rA0) * D1 + kn + qA0 * 8]);
            pb1 = *reinterpret_cast<const uint4*>(&g_w2b[(size_t)(col0 + rA1) * D1 + kn + qA1 * 8]);
        }

#pragma unroll
        for (int kh = 0; kh < 2; kh++) {
            uint32_t af[4][4], bf[4][2];
#pragma unroll
            for (int mt = 0; mt < 4; mt++) {
                int r = wm * 64 + mt * 16 + (lane & 15);
                int c = kh * 16 + (lane >> 4) * 8;
                uint32_t a = smem_u32(&As[r][c]);
                asm volatile("ldmatrix.sync.aligned.m8n8.x4.shared.b16 {%0,%1,%2,%3}, [%4];"
                    : "=r"(af[mt][0]), "=r"(af[mt][1]), "=r"(af[mt][2]), "=r"(af[mt][3]) : "r"(a));
            }
#pragma unroll
            for (int nt = 0; nt < 4; nt++) {
                int r = wn * 32 + nt * 8 + (lane & 7);
                int c = kh * 16 + ((lane >> 3) & 1) * 8;
                uint32_t a = smem_u32(&Bs[r][c]);
                asm volatile("ldmatrix.sync.aligned.m8n8.x2.shared.b16 {%0,%1}, [%2];"
                    : "=r"(bf[nt][0]), "=r"(bf[nt][1]) : "r"(a));
            }
#pragma unroll
            for (int mt = 0; mt < 4; mt++)
#pragma unroll
                for (int nt = 0; nt < 4; nt++)
                    asm volatile(
                        "mma.sync.aligned.m16n8k16.row.col.f32.bf16.bf16.f32 "
                        "{%0,%1,%2,%3},{%4,%5,%6,%7},{%8,%9},{%0,%1,%2,%3};"
                        : "+f"(acc[mt][nt][0]), "+f"(acc[mt][nt][1]),
                          "+f"(acc[mt][nt][2]), "+f"(acc[mt][nt][3])
                        : "r"(af[mt][0]), "r"(af[mt][1]), "r"(af[mt][2]), "r"(af[mt][3]),
                          "r"(bf[nt][0]), "r"(bf[nt][1]));
        }
        __syncthreads();
    }

    // epilogue
#pragma unroll
    for (int mt = 0; mt < 4; mt++) {
        int rr = row0 + wm * 64 + mt * 16 + (lane >> 2);
#pragma unroll
        for (int nt = 0; nt < 4; nt++) {
            int cc = col0 + wn * 32 + nt * 8 + 2 * (lane & 3);
            if (rr < NN)
                *reinterpret_cast<float2*>(&g_h2[(size_t)rr * HHID + cc]) =
                    make_float2(acc[mt][nt][0], acc[mt][nt][1]);
            if (rr + 8 < NN)
                *reinterpret_cast<float2*>(&g_h2[(size_t)(rr + 8) * HHID + cc]) =
                    make_float2(acc[mt][nt][2], acc[mt][nt][3]);
        }
    }
}

// ---------------- attention logits layer 2 + self ex + den init --------
__global__ void k_att2(const float* __restrict__ as, const float* __restrict__ adv) {
    int wid = threadIdx.x >> 5, lane = threadIdx.x & 31;
    int d = blockIdx.x * 4 + wid;
    if (d >= NN) return;
    const float4* h4  = reinterpret_cast<const float4*>(g_h2 + (size_t)d * HHID);
    const float4* as4 = reinterpret_cast<const float4*>(as);
    const float4* ad4 = reinterpret_cast<const float4*>(adv);
    float ps = 0.f, pd = 0.f;
#pragma unroll
    for (int t = 0; t < 2; t++) {
        int p = lane + 32 * t;
        float4 f = h4[p];
        float4 a = as4[p], b = ad4[p];
        ps += f.x * a.x + f.y * a.y + f.z * a.z + f.w * a.w;
        pd += f.x * b.x + f.y * b.y + f.z * b.z + f.w * b.w;
    }
#pragma unroll
    for (int o = 16; o; o >>= 1) {
        ps += __shfl_xor_sync(0xffffffffu, ps, o);
        pd += __shfl_xor_sync(0xffffffffu, pd, o);
    }
    if (lane == 0) {
        g_as2[d] = ps; g_ad2[d] = pd;
        float e = ps + pd;
        e = e > 0.f ? e : 0.2f * e;
        float ex = expf(e);
        g_exself2[d] = ex;
        g_den2[d] = ex;
    }
}

// ---------------- edge kernel layer 2 ----------------------------------
__global__ void k_edge2(const int* __restrict__ ei) {
    int i = blockIdx.x * blockDim.x + threadIdx.x;
    if (i >= EE) return;
    int s = ei[i], d = ei[EE + i];
    float e = g_as2[s] + g_ad2[d];
    e = e > 0.f ? e : 0.2f * e;
    float ex = expf(e);
    g_ex2s[g_pos[i]] = ex;
    atomicAdd(&g_den2[d], ex);
}

// ---------------- layer-2 aggregation + ReLU + mean pool ---------------
__global__ void k_agg2(const float* __restrict__ b2) {
    int d = blockIdx.x, tid = threadIdx.x;
    int beg = g_offs[d], cnt = g_offs[d + 1] - beg;
    float acc = g_exself2[d] * g_h2[(size_t)d * HHID + tid];
#pragma unroll 4
    for (int i = 0; i < cnt; i++) {
        int s = g_srcs[beg + i];
        acc += g_ex2s[beg + i] * g_h2[(size_t)s * HHID + tid];
    }
    float inv = 1.f / (g_den2[d] + 1e-16f);
    float v = acc * inv + b2[tid];
    v = v > 0.f ? v : 0.f;
    atomicAdd(&g_pooled[tid], v * (1.0f / NN));
}

// ---------------- final MLP ----------------
__global__ void k_final(const float* __restrict__ Wv1, const float* __restrict__ bv1,
                        const float* __restrict__ Wv2, const float* __restrict__ bv2,
                        float* __restrict__ out) {
    __shared__ float sp[HHID];
    __shared__ float wred[4];
    int t = threadIdx.x;   // 128 threads
    for (int c = t; c < HHID; c += 128) sp[c] = g_pooled[c];
    __syncthreads();
    float a = 0.f;
    for (int k = 0; k < HHID; k++) a += sp[k] * Wv1[k * 128 + t];
    a += bv1[t];
    float g = a * normcdff(a);
    float v = g * Wv2[t];
    int lane = t & 31, wid = t >> 5;
#pragma unroll
    for (int o = 16; o; o >>= 1) v += __shfl_xor_sync(0xffffffffu, v, o);
    if (lane == 0) wred[wid] = v;
    __syncthreads();
    if (t == 0) out[0] = wred[0] + wred[1] + wred[2] + wred[3] + bv2[0];
}

// ---------------- launch ----------------
extern "C" void kernel_launch(void* const* d_in, const int* in_sizes, int n_in,
                              void* d_out, int out_size) {
    const float* x       = (const float*)d_in[0];
    const int*   ei      = (const int*)  d_in[1];
    // d_in[2] edge_attr unused (GATConv built without edge_dim)
    const float* W1      = (const float*)d_in[3];
    const float* att_s1  = (const float*)d_in[4];
    const float* att_d1  = (const float*)d_in[5];
    const float* b1      = (const float*)d_in[6];
    const float* W2      = (const float*)d_in[7];
    const float* att_s2  = (const float*)d_in[8];
    const float* att_d2  = (const float*)d_in[9];
    const float* b2      = (const float*)d_in[10];
    const float* Wv1     = (const float*)d_in[11];
    const float* bv1     = (const float*)d_in[12];
    const float* Wv2     = (const float*)d_in[13];
    const float* bv2     = (const float*)d_in[14];
    float* out = (float*)d_out;

    k_zero<<<(NN + 255) / 256, 256>>>();
    k_hist<<<(EE + 255) / 256, 256>>>(ei);
    k_scan<<<1, 1024>>>();
    k_scatter<<<(EE + 255) / 256, 256>>>(ei);

    dim3 gw(D1 / 32, HHID / 32);
    k_prepW2<<<gw, 256>>>(W2);

    dim3 g1((NN + NPB - 1) / NPB, 2);
    k_gemm1<<<g1, 256>>>(x, W1);
    k_att1<<<NN, 128>>>(att_s1, att_d1);
    k_edge1<<<(EE + 255) / 256, 256>>>(ei);
    k_agg1<<<NN, 256>>>(b1);

    dim3 g2((NN + MM_BM - 1) / MM_BM, HHID / MM_BN);
    k_gemm2<<<g2, 256>>>(0);
    k_att2<<<(NN + 3) / 4, 128>>>(att_s2, att_d2);
    k_edge2<<<(EE + 255) / 256, 256>>>(ei);
    k_agg2<<<NN, 256>>>(b2);

    k_final<<<1, 128>>>(Wv1, bv1, Wv2, bv2, out);
}

// round 11
// speedup vs baseline: 2.0411x; 1.0835x over previous
#include <cuda_runtime.h>
#include <cuda_fp16.h>
#include <math.h>
#include <stdint.h>

#define NN 10000
#define EE 160000
#define FIN 70
#define KP 80            // FIN padded to multiple of 16
#define HHID 256
#define D1 1024          // HEADS*HID

typedef unsigned long long u64;

__device__ __forceinline__ uint32_t smem_u32(const void* p) {
    uint32_t a;
    asm("{ .reg .u64 t; cvta.to.shared.u64 t, %1; cvt.u32.u64 %0, t; }" : "=r"(a) : "l"(p));
    return a;
}
__device__ __forceinline__ float4 h4_to_f4(u64 v) {
    __half2 lo = reinterpret_cast<__half2*>(&v)[0];
    __half2 hi = reinterpret_cast<__half2*>(&v)[1];
    float2 a = __half22float2(lo), b = __half22float2(hi);
    return make_float4(a.x, a.y, b.x, b.y);
}

// ---------------- device scratch (no allocations allowed) ----------------
__device__ __align__(16) __half g_h1h[NN * D1];   // layer-1 linear out (fp16)
__device__ __align__(16) __half g_x1h[NN * D1];   // relu(agg1+b1) fp16 (GEMM2 A)
__device__ __align__(16) __half g_w1h[D1 * KP];   // W1^T fp16 [n][k], k padded to 80
__device__ __align__(16) __half g_w2h[HHID * D1]; // W2^T fp16 [n][k]
__device__ __align__(16) float g_as1[NN * 4];
__device__ __align__(16) float g_ad1[NN * 4];
__device__ __align__(16) float g_h2[NN * HHID];   // layer-2 linear out (fp32)
__device__ float g_as2[NN];
__device__ float g_ad2[NN];
__device__ __align__(16) float g_ex1s[EE * 4];    // exp(leaky) per edge, DST-SORTED
__device__ float g_ex2s[EE];
__device__ __align__(16) float g_exself1[NN * 4];
__device__ __align__(16) float g_den1[NN * 4];
__device__ float g_exself2[NN];
__device__ float g_den2[NN];
__device__ float g_pooled[HHID];
__device__ int   g_deg[NN];
__device__ int   g_offs[NN + 1];
__device__ int   g_cursor[NN];
__device__ int   g_srcs[EE];
__device__ int   g_pos[EE];      // original edge -> sorted slot

// ---------------- small utils ----------------
__global__ void k_zero() {
    int i = blockIdx.x * blockDim.x + threadIdx.x;
    if (i < NN)  g_deg[i] = 0;
    if (i < HHID) g_pooled[i] = 0.f;
}

__global__ void k_hist(const int* __restrict__ ei) {
    int i = blockIdx.x * blockDim.x + threadIdx.x;
    if (i < EE) atomicAdd(&g_deg[ei[EE + i]], 1);
}

__global__ void k_scan() {
    __shared__ int sbuf[1024];
    int t = threadIdx.x;
    int base = t * 10;
    int loc[10];
    int sum = 0;
#pragma unroll
    for (int q = 0; q < 10; q++) {
        int idx = base + q;
        int v = (idx < NN) ? g_deg[idx] : 0;
        loc[q] = sum; sum += v;
    }
    sbuf[t] = sum;
    __syncthreads();
    for (int off = 1; off < 1024; off <<= 1) {
        int tmp = (t >= off) ? sbuf[t - off] : 0;
        __syncthreads();
        sbuf[t] += tmp;
        __syncthreads();
    }
    int excl = sbuf[t] - sum;
#pragma unroll
    for (int q = 0; q < 10; q++) {
        int idx = base + q;
        if (idx < NN) { int o = excl + loc[q]; g_offs[idx] = o; g_cursor[idx] = o; }
    }
    if (t == 1023) g_offs[NN] = sbuf[1023];
}

__global__ void k_scatter(const int* __restrict__ ei) {
    int i = blockIdx.x * blockDim.x + threadIdx.x;
    if (i < EE) {
        int dnode = ei[EE + i];
        int pos = atomicAdd(&g_cursor[dnode], 1);
        g_srcs[pos] = ei[i];
        g_pos[i] = pos;
    }
}

// ---------------- W1 [70,1024] fp32 -> g_w1h [1024][80] fp16 ------------
__global__ void k_prepW1(const float* __restrict__ W1) {
    int id = blockIdx.x * blockDim.x + threadIdx.x;  // k-major over [KP][D1]
    if (id >= KP * D1) return;
    int k = id >> 10, n = id & 1023;
    float v = (k < FIN) ? W1[k * D1 + n] : 0.f;
    g_w1h[(size_t)n * KP + k] = __float2half(v);
}

// ---------------- W2 [1024,256] fp32 -> g_w2h [256][1024] fp16 ----------
__global__ void k_prepW2(const float* __restrict__ W2) {
    __shared__ float t[32][33];
    int k0 = blockIdx.x * 32, n0 = blockIdx.y * 32;
    int tx = threadIdx.x & 31, ty = threadIdx.x >> 5;   // 256 threads
#pragma unroll
    for (int i = 0; i < 4; i++)
        t[ty + 8 * i][tx] = W2[(k0 + ty + 8 * i) * HHID + n0 + tx];
    __syncthreads();
#pragma unroll
    for (int i = 0; i < 4; i++)
        g_w2h[(size_t)(n0 + ty + 8 * i) * D1 + k0 + tx] = __float2half(t[tx][ty + 8 * i]);
}

// ---------------- GEMM1 via HMMA: x[N,70] @ W1 -> g_h1h (fp16) ----------
// A = x fp32 -> fp16 smem [128][88], B = g_w1h [128][88], K=80 (5 chunks)
#define G1_LDS 88
__global__ void __launch_bounds__(256) k_gemm1(const float* __restrict__ x) {
    __shared__ __align__(16) __half As[128][G1_LDS];
    __shared__ __align__(16) __half Bs[128][G1_LDS];
    int tid = threadIdx.x, lane = tid & 31, w = tid >> 5;
    int wm = w >> 2, wn = w & 3;
    int row0 = blockIdx.x * 128;
    int col0 = blockIdx.y * 128;

    // load A: 128 rows x 70 fp32 -> fp16, pad to 80
    for (int idx = tid; idx < 128 * KP; idx += 256) {
        int r = idx / KP, c = idx - r * KP;
        float v = 0.f;
        if (c < FIN && row0 + r < NN) v = x[(size_t)(row0 + r) * FIN + c];
        As[r][c] = __float2half(v);
    }
    // load B: 128 rows x 80 halves (10 uint4 per row)
    for (int idx = tid; idx < 128 * 10; idx += 256) {
        int r = idx / 10, q = idx - r * 10;
        *reinterpret_cast<uint4*>(&Bs[r][q * 8]) =
            *reinterpret_cast<const uint4*>(&g_w1h[(size_t)(col0 + r) * KP + q * 8]);
    }
    __syncthreads();

    float acc[4][4][4];
#pragma unroll
    for (int i = 0; i < 4; i++)
#pragma unroll
        for (int j = 0; j < 4; j++)
#pragma unroll
            for (int q = 0; q < 4; q++) acc[i][j][q] = 0.f;

#pragma unroll
    for (int kh = 0; kh < 5; kh++) {
        uint32_t af[4][4], bf[4][2];
#pragma unroll
        for (int mt = 0; mt < 4; mt++) {
            int r = wm * 64 + mt * 16 + (lane & 15);
            int c = kh * 16 + (lane >> 4) * 8;
            uint32_t a = smem_u32(&As[r][c]);
            asm volatile("ldmatrix.sync.aligned.m8n8.x4.shared.b16 {%0,%1,%2,%3}, [%4];"
                : "=r"(af[mt][0]), "=r"(af[mt][1]), "=r"(af[mt][2]), "=r"(af[mt][3]) : "r"(a));
        }
#pragma unroll
        for (int nt = 0; nt < 4; nt++) {
            int r = wn * 32 + nt * 8 + (lane & 7);
            int c = kh * 16 + ((lane >> 3) & 1) * 8;
            uint32_t a = smem_u32(&Bs[r][c]);
            asm volatile("ldmatrix.sync.aligned.m8n8.x2.shared.b16 {%0,%1}, [%2];"
                : "=r"(bf[nt][0]), "=r"(bf[nt][1]) : "r"(a));
        }
#pragma unroll
        for (int mt = 0; mt < 4; mt++)
#pragma unroll
            for (int nt = 0; nt < 4; nt++)
                asm volatile(
                    "mma.sync.aligned.m16n8k16.row.col.f32.f16.f16.f32 "
                    "{%0,%1,%2,%3},{%4,%5,%6,%7},{%8,%9},{%0,%1,%2,%3};"
                    : "+f"(acc[mt][nt][0]), "+f"(acc[mt][nt][1]),
                      "+f"(acc[mt][nt][2]), "+f"(acc[mt][nt][3])
                    : "r"(af[mt][0]), "r"(af[mt][1]), "r"(af[mt][2]), "r"(af[mt][3]),
                      "r"(bf[nt][0]), "r"(bf[nt][1]));
    }

#pragma unroll
    for (int mt = 0; mt < 4; mt++) {
        int rr = row0 + wm * 64 + mt * 16 + (lane >> 2);
#pragma unroll
        for (int nt = 0; nt < 4; nt++) {
            int cc = col0 + wn * 32 + nt * 8 + 2 * (lane & 3);
            if (rr < NN)
                *reinterpret_cast<__half2*>(&g_h1h[(size_t)rr * D1 + cc]) =
                    __floats2half2_rn(acc[mt][nt][0], acc[mt][nt][1]);
            if (rr + 8 < NN)
                *reinterpret_cast<__half2*>(&g_h1h[(size_t)(rr + 8) * D1 + cc]) =
                    __floats2half2_rn(acc[mt][nt][2], acc[mt][nt][3]);
        }
    }
}

// ---------------- attention logits layer 1 + self-loop ex + den init ---
__global__ void k_att1(const float* __restrict__ as, const float* __restrict__ adv) {
    int wid = threadIdx.x >> 5, lane = threadIdx.x & 31;
    int d = blockIdx.x;
    const u64* hb = reinterpret_cast<const u64*>(g_h1h + (size_t)d * D1 + wid * 256);
    const float4* as4 = reinterpret_cast<const float4*>(as  + wid * 256);
    const float4* ad4 = reinterpret_cast<const float4*>(adv + wid * 256);
    float ps = 0.f, pd = 0.f;
#pragma unroll
    for (int t = 0; t < 2; t++) {
        int p = lane + 32 * t;
        float4 f = h4_to_f4(hb[p]);
        float4 a = as4[p], b = ad4[p];
        ps += f.x * a.x + f.y * a.y + f.z * a.z + f.w * a.w;
        pd += f.x * b.x + f.y * b.y + f.z * b.z + f.w * b.w;
    }
#pragma unroll
    for (int o = 16; o; o >>= 1) {
        ps += __shfl_xor_sync(0xffffffffu, ps, o);
        pd += __shfl_xor_sync(0xffffffffu, pd, o);
    }
    if (lane == 0) {
        g_as1[d * 4 + wid] = ps; g_ad1[d * 4 + wid] = pd;
        float e = ps + pd;
        e = e > 0.f ? e : 0.2f * e;
        float ex = expf(e);
        g_exself1[d * 4 + wid] = ex;
        g_den1[d * 4 + wid] = ex;
    }
}

// ---------------- edge kernel layer 1: ex (sorted) + denom atomics -----
__global__ void k_edge1(const int* __restrict__ ei) {
    int i = blockIdx.x * blockDim.x + threadIdx.x;
    if (i >= EE) return;
    int s = ei[i], d = ei[EE + i];
    float4 a = *reinterpret_cast<const float4*>(&g_as1[s * 4]);
    float4 b = *reinterpret_cast<const float4*>(&g_ad1[d * 4]);
    float e0 = a.x + b.x; e0 = e0 > 0.f ? e0 : 0.2f * e0; e0 = expf(e0);
    float e1 = a.y + b.y; e1 = e1 > 0.f ? e1 : 0.2f * e1; e1 = expf(e1);
    float e2 = a.z + b.z; e2 = e2 > 0.f ? e2 : 0.2f * e2; e2 = expf(e2);
    float e3 = a.w + b.w; e3 = e3 > 0.f ? e3 : 0.2f * e3; e3 = expf(e3);
    int pos = g_pos[i];
    *reinterpret_cast<float4*>(&g_ex1s[(size_t)pos * 4]) = make_float4(e0, e1, e2, e3);
    atomicAdd(&g_den1[d * 4 + 0], e0);
    atomicAdd(&g_den1[d * 4 + 1], e1);
    atomicAdd(&g_den1[d * 4 + 2], e2);
    atomicAdd(&g_den1[d * 4 + 3], e3);
}

// ---------------- layer-1 aggregation: single pass, vectorized ---------
// thread t handles channels [4t, 4t+4) -> one head per thread (h = t>>6)
__global__ void k_agg1(const float* __restrict__ b1) {
    int d = blockIdx.x, t = threadIdx.x;
    int beg = g_offs[d], cnt = g_offs[d + 1] - beg;
    int h = t >> 6;
    const u64* hb = reinterpret_cast<const u64*>(g_h1h);

    // self-loop term
    float ex = g_exself1[d * 4 + h];
    float4 f = h4_to_f4(hb[(size_t)d * 256 + t]);
    float ax = ex * f.x, ay = ex * f.y, az = ex * f.z, aw = ex * f.w;

#pragma unroll 4
    for (int i = 0; i < cnt; i++) {
        int s = g_srcs[beg + i];
        float e = g_ex1s[(size_t)(beg + i) * 4 + h];
        float4 g = h4_to_f4(hb[(size_t)s * 256 + t]);
        ax += e * g.x; ay += e * g.y; az += e * g.z; aw += e * g.w;
    }

    float inv = 1.f / (g_den1[d * 4 + h] + 1e-16f);
    float4 bb = *reinterpret_cast<const float4*>(&b1[4 * t]);
    __half2 lo = __floats2half2_rn(fmaxf(ax * inv + bb.x, 0.f),
                                   fmaxf(ay * inv + bb.y, 0.f));
    __half2 hi = __floats2half2_rn(fmaxf(az * inv + bb.z, 0.f),
                                   fmaxf(aw * inv + bb.w, 0.f));
    u64 outv;
    reinterpret_cast<__half2*>(&outv)[0] = lo;
    reinterpret_cast<__half2*>(&outv)[1] = hi;
    *reinterpret_cast<u64*>(&g_x1h[(size_t)d * D1 + 4 * t]) = outv;
}

// ---------------- GEMM2 via mma.sync (HMMA fp16) ------------------------
#define MM_BM 128
#define MM_BN 128
#define MM_BK 32
#define MM_LDS 40      // row stride in halves (32 + 8 pad)
__global__ void __launch_bounds__(256) k_gemm2(int dummy) {
    __shared__ __align__(16) __half As[MM_BM][MM_LDS];
    __shared__ __align__(16) __half Bs[MM_BN][MM_LDS];
    int tid = threadIdx.x, lane = tid & 31, w = tid >> 5;
    int wm = w >> 2, wn = w & 3;                 // warp tile: 64m x 32n
    int row0 = blockIdx.x * MM_BM;
    int col0 = blockIdx.y * MM_BN;

    float acc[4][4][4];
#pragma unroll
    for (int i = 0; i < 4; i++)
#pragma unroll
        for (int j = 0; j < 4; j++)
#pragma unroll
            for (int q = 0; q < 4; q++) acc[i][j][q] = 0.f;

    int rA0 = (tid + 0)   >> 2, qA0 = (tid + 0)   & 3;
    int rA1 = (tid + 256) >> 2, qA1 = (tid + 256) & 3;

    uint4 pa0, pa1, pb0, pb1;
    {
        pa0 = make_uint4(0, 0, 0, 0); pa1 = make_uint4(0, 0, 0, 0);
        if (row0 + rA0 < NN)
            pa0 = *reinterpret_cast<const uint4*>(&g_x1h[(size_t)(row0 + rA0) * D1 + qA0 * 8]);
        if (row0 + rA1 < NN)
            pa1 = *reinterpret_cast<const uint4*>(&g_x1h[(size_t)(row0 + rA1) * D1 + qA1 * 8]);
        pb0 = *reinterpret_cast<const uint4*>(&g_w2h[(size_t)(col0 + rA0) * D1 + qA0 * 8]);
        pb1 = *reinterpret_cast<const uint4*>(&g_w2h[(size_t)(col0 + rA1) * D1 + qA1 * 8]);
    }

    for (int kc = 0; kc < D1; kc += MM_BK) {
        *reinterpret_cast<uint4*>(&As[rA0][qA0 * 8]) = pa0;
        *reinterpret_cast<uint4*>(&As[rA1][qA1 * 8]) = pa1;
        *reinterpret_cast<uint4*>(&Bs[rA0][qA0 * 8]) = pb0;
        *reinterpret_cast<uint4*>(&Bs[rA1][qA1 * 8]) = pb1;
        __syncthreads();

        if (kc + MM_BK < D1) {
            int kn = kc + MM_BK;
            pa0 = make_uint4(0, 0, 0, 0); pa1 = make_uint4(0, 0, 0, 0);
            if (row0 + rA0 < NN)
                pa0 = *reinterpret_cast<const uint4*>(&g_x1h[(size_t)(row0 + rA0) * D1 + kn + qA0 * 8]);
            if (row0 + rA1 < NN)
                pa1 = *reinterpret_cast<const uint4*>(&g_x1h[(size_t)(row0 + rA1) * D1 + kn + qA1 * 8]);
            pb0 = *reinterpret_cast<const uint4*>(&g_w2h[(size_t)(col0 + rA0) * D1 + kn + qA0 * 8]);
            pb1 = *reinterpret_cast<const uint4*>(&g_w2h[(size_t)(col0 + rA1) * D1 + kn + qA1 * 8]);
        }

#pragma unroll
        for (int kh = 0; kh < 2; kh++) {
            uint32_t af[4][4], bf[4][2];
#pragma unroll
            for (int mt = 0; mt < 4; mt++) {
                int r = wm * 64 + mt * 16 + (lane & 15);
                int c = kh * 16 + (lane >> 4) * 8;
                uint32_t a = smem_u32(&As[r][c]);
                asm volatile("ldmatrix.sync.aligned.m8n8.x4.shared.b16 {%0,%1,%2,%3}, [%4];"
                    : "=r"(af[mt][0]), "=r"(af[mt][1]), "=r"(af[mt][2]), "=r"(af[mt][3]) : "r"(a));
            }
#pragma unroll
            for (int nt = 0; nt < 4; nt++) {
                int r = wn * 32 + nt * 8 + (lane & 7);
                int c = kh * 16 + ((lane >> 3) & 1) * 8;
                uint32_t a = smem_u32(&Bs[r][c]);
                asm volatile("ldmatrix.sync.aligned.m8n8.x2.shared.b16 {%0,%1}, [%2];"
                    : "=r"(bf[nt][0]), "=r"(bf[nt][1]) : "r"(a));
            }
#pragma unroll
            for (int mt = 0; mt < 4; mt++)
#pragma unroll
                for (int nt = 0; nt < 4; nt++)
                    asm volatile(
                        "mma.sync.aligned.m16n8k16.row.col.f32.f16.f16.f32 "
                        "{%0,%1,%2,%3},{%4,%5,%6,%7},{%8,%9},{%0,%1,%2,%3};"
                        : "+f"(acc[mt][nt][0]), "+f"(acc[mt][nt][1]),
                          "+f"(acc[mt][nt][2]), "+f"(acc[mt][nt][3])
                        : "r"(af[mt][0]), "r"(af[mt][1]), "r"(af[mt][2]), "r"(af[mt][3]),
                          "r"(bf[nt][0]), "r"(bf[nt][1]));
        }
        __syncthreads();
    }

#pragma unroll
    for (int mt = 0; mt < 4; mt++) {
        int rr = row0 + wm * 64 + mt * 16 + (lane >> 2);
#pragma unroll
        for (int nt = 0; nt < 4; nt++) {
            int cc = col0 + wn * 32 + nt * 8 + 2 * (lane & 3);
            if (rr < NN)
                *reinterpret_cast<float2*>(&g_h2[(size_t)rr * HHID + cc]) =
                    make_float2(acc[mt][nt][0], acc[mt][nt][1]);
            if (rr + 8 < NN)
                *reinterpret_cast<float2*>(&g_h2[(size_t)(rr + 8) * HHID + cc]) =
                    make_float2(acc[mt][nt][2], acc[mt][nt][3]);
        }
    }
}

// ---------------- attention logits layer 2 + self ex + den init --------
__global__ void k_att2(const float* __restrict__ as, const float* __restrict__ adv) {
    int wid = threadIdx.x >> 5, lane = threadIdx.x & 31;
    int d = blockIdx.x * 4 + wid;
    if (d >= NN) return;
    const float4* h4  = reinterpret_cast<const float4*>(g_h2 + (size_t)d * HHID);
    const float4* as4 = reinterpret_cast<const float4*>(as);
    const float4* ad4 = reinterpret_cast<const float4*>(adv);
    float ps = 0.f, pd = 0.f;
#pragma unroll
    for (int t = 0; t < 2; t++) {
        int p = lane + 32 * t;
        float4 f = h4[p];
        float4 a = as4[p], b = ad4[p];
        ps += f.x * a.x + f.y * a.y + f.z * a.z + f.w * a.w;
        pd += f.x * b.x + f.y * b.y + f.z * b.z + f.w * b.w;
    }
#pragma unroll
    for (int o = 16; o; o >>= 1) {
        ps += __shfl_xor_sync(0xffffffffu, ps, o);
        pd += __shfl_xor_sync(0xffffffffu, pd, o);
    }
    if (lane == 0) {
        g_as2[d] = ps; g_ad2[d] = pd;
        float e = ps + pd;
        e = e > 0.f ? e : 0.2f * e;
        float ex = expf(e);
        g_exself2[d] = ex;
        g_den2[d] = ex;
    }
}

// ---------------- edge kernel layer 2 ----------------------------------
__global__ void k_edge2(const int* __restrict__ ei) {
    int i = blockIdx.x * blockDim.x + threadIdx.x;
    if (i >= EE) return;
    int s = ei[i], d = ei[EE + i];
    float e = g_as2[s] + g_ad2[d];
    e = e > 0.f ? e : 0.2f * e;
    float ex = expf(e);
    g_ex2s[g_pos[i]] = ex;
    atomicAdd(&g_den2[d], ex);
}

// ---------------- layer-2 aggregation + ReLU + mean pool ---------------
__global__ void k_agg2(const float* __restrict__ b2) {
    int d = blockIdx.x, tid = threadIdx.x;
    int beg = g_offs[d], cnt = g_offs[d + 1] - beg;
    float acc = g_exself2[d] * g_h2[(size_t)d * HHID + tid];
#pragma unroll 4
    for (int i = 0; i < cnt; i++) {
        int s = g_srcs[beg + i];
        acc += g_ex2s[beg + i] * g_h2[(size_t)s * HHID + tid];
    }
    float inv = 1.f / (g_den2[d] + 1e-16f);
    float v = acc * inv + b2[tid];
    v = v > 0.f ? v : 0.f;
    atomicAdd(&g_pooled[tid], v * (1.0f / NN));
}

// ---------------- final MLP ----------------
__global__ void k_final(const float* __restrict__ Wv1, const float* __restrict__ bv1,
                        const float* __restrict__ Wv2, const float* __restrict__ bv2,
                        float* __restrict__ out) {
    __shared__ float sp[HHID];
    __shared__ float wred[4];
    int t = threadIdx.x;   // 128 threads
    for (int c = t; c < HHID; c += 128) sp[c] = g_pooled[c];
    __syncthreads();
    float a = 0.f;
    for (int k = 0; k < HHID; k++) a += sp[k] * Wv1[k * 128 + t];
    a += bv1[t];
    float g = a * normcdff(a);
    float v = g * Wv2[t];
    int lane = t & 31, wid = t >> 5;
#pragma unroll
    for (int o = 16; o; o >>= 1) v += __shfl_xor_sync(0xffffffffu, v, o);
    if (lane == 0) wred[wid] = v;
    __syncthreads();
    if (t == 0) out[0] = wred[0] + wred[1] + wred[2] + wred[3] + bv2[0];
}

// ---------------- launch ----------------
extern "C" void kernel_launch(void* const* d_in, const int* in_sizes, int n_in,
                              void* d_out, int out_size) {
    const float* x       = (const float*)d_in[0];
    const int*   ei      = (const int*)  d_in[1];
    // d_in[2] edge_attr unused (GATConv built without edge_dim)
    const float* W1      = (const float*)d_in[3];
    const float* att_s1  = (const float*)d_in[4];
    const float* att_d1  = (const float*)d_in[5];
    const float* b1      = (const float*)d_in[6];
    const float* W2      = (const float*)d_in[7];
    const float* att_s2  = (const float*)d_in[8];
    const float* att_d2  = (const float*)d_in[9];
    const float* b2      = (const float*)d_in[10];
    const float* Wv1     = (const float*)d_in[11];
    const float* bv1     = (const float*)d_in[12];
    const float* Wv2     = (const float*)d_in[13];
    const float* bv2     = (const float*)d_in[14];
    float* out = (float*)d_out;

    k_zero<<<(NN + 255) / 256, 256>>>();
    k_hist<<<(EE + 255) / 256, 256>>>(ei);
    k_scan<<<1, 1024>>>();
    k_scatter<<<(EE + 255) / 256, 256>>>(ei);

    k_prepW1<<<(KP * D1 + 255) / 256, 256>>>(W1);
    dim3 gw(D1 / 32, HHID / 32);
    k_prepW2<<<gw, 256>>>(W2);

    dim3 g1((NN + 127) / 128, D1 / 128);
    k_gemm1<<<g1, 256>>>(x);
    k_att1<<<NN, 128>>>(att_s1, att_d1);
    k_edge1<<<(EE + 255) / 256, 256>>>(ei);
    k_agg1<<<NN, 256>>>(b1);

    dim3 g2((NN + MM_BM - 1) / MM_BM, HHID / MM_BN);
    k_gemm2<<<g2, 256>>>(0);
    k_att2<<<(NN + 3) / 4, 128>>>(att_s2, att_d2);
    k_edge2<<<(EE + 255) / 256, 256>>>(ei);
    k_agg2<<<NN, 256>>>(b2);

    k_final<<<1, 128>>>(Wv1, bv1, Wv2, bv2, out);
}